// round 14
// baseline (speedup 1.0000x reference)
#include <cuda_runtime.h>
#include <cuda_fp16.h>
#include <math.h>
#include <stdint.h>

#define NB 512
#define NH 1024
#define NS 64
#define NM 10
#define CAT_LD 1056
#define NBNH (NB * NH)
#define G3 (3 * NH)
#define NJOBS 12
#define W4 786432                     // G3*NH/4

// ---------------- scratch (device globals) ----------------------------------
__device__ __align__(1024) __half g_preWh[NH * CAT_LD];
__device__ __align__(1024) __half g_Wih0h[G3 * NH];
__device__ __align__(1024) __half g_Wih1h[G3 * NH];
__device__ __align__(1024) __half g_hLh[2 * NBNH];
__device__ __align__(1024) float  g_upart[8 * NBNH];
__device__ __align__(1024) __half g_cath[NB * CAT_LD];
__device__ __align__(1024) float  g_xpart[6 * NBNH];
__device__ __align__(1024) __half g_x0h[NBNH];
__device__ __align__(1024) __half g_h0h[NBNH];
__device__ __align__(1024) float  g_gi0A[NB * G3];
__device__ __align__(1024) float  g_gi0B[NB * G3];
__device__ __align__(1024) float  g_gh0[NB * G3];
__device__ __align__(1024) float  g_gh1[NB * G3];
__device__ __align__(1024) float  g_gi1A[NB * G3];
__device__ __align__(1024) float  g_gi1B[NB * G3];
__device__ __align__(1024) float  g_gi1C[NB * G3];

struct Jobs {
    const float* A[NJOBS]; const float* B[NJOBS];
    const float* bias[NJOBS]; float* C[NJOBS];
    int lda[NJOBS], ldb[NJOBS], ldc[NJOBS], nchunk[NJOBS], nx[NJOBS];
    int split[NJOBS], nn[NJOBS];
    // conversion-job sources (split==2)
    const float *cWih0, *cWhh0, *cWih1, *cWhh1, *cHL, *cPreW;
};
struct JobsH {
    const __half* A[NJOBS]; const __half* B[NJOBS];
    const float* bias[NJOBS]; float* C[NJOBS];
    int lda[NJOBS], ldb[NJOBS], ldc[NJOBS], nchunk[NJOBS], nx[NJOBS];
};

// ---------------- helpers ----------------------------------------------------
__device__ __forceinline__ void gdc_launch() {
    asm volatile("griddepcontrol.launch_dependents;" ::: "memory");
}
__device__ __forceinline__ void gdc_wait() {
    asm volatile("griddepcontrol.wait;" ::: "memory");
}
__device__ __forceinline__ uint32_t smem_u32(const void* p) {
    uint32_t a;
    asm("{ .reg .u64 t; cvta.to.shared.u64 t, %1; cvt.u32.u64 %0, t; }"
        : "=r"(a) : "l"(p));
    return a;
}
__device__ __forceinline__ uint32_t tf32_rna(float x) {
    uint32_t r;
    asm("cvt.rna.tf32.f32 %0, %1;" : "=r"(r) : "f"(x));
    return r;
}
__device__ __forceinline__ void mma_tf32(float* c, uint32_t a0, uint32_t a1,
                                         uint32_t a2, uint32_t a3,
                                         uint32_t b0, uint32_t b1) {
    asm volatile(
        "mma.sync.aligned.m16n8k8.row.col.f32.tf32.tf32.f32 "
        "{%0,%1,%2,%3}, {%4,%5,%6,%7}, {%8,%9}, {%0,%1,%2,%3};"
        : "+f"(c[0]), "+f"(c[1]), "+f"(c[2]), "+f"(c[3])
        : "r"(a0), "r"(a1), "r"(a2), "r"(a3), "r"(b0), "r"(b1));
}
__device__ __forceinline__ void mma_f16(float* c, uint32_t a0, uint32_t a1,
                                        uint32_t a2, uint32_t a3,
                                        uint32_t b0, uint32_t b1) {
    asm volatile(
        "mma.sync.aligned.m16n8k16.row.col.f32.f16.f16.f32 "
        "{%0,%1,%2,%3}, {%4,%5,%6,%7}, {%8,%9}, {%0,%1,%2,%3};"
        : "+f"(c[0]), "+f"(c[1]), "+f"(c[2]), "+f"(c[3])
        : "r"(a0), "r"(a1), "r"(a2), "r"(a3), "r"(b0), "r"(b1));
}
__device__ __forceinline__ void cp16(uint32_t dst, const void* src) {
    asm volatile("cp.async.cg.shared.global [%0], [%1], 16;"
                 :: "r"(dst), "l"(src));
}
__device__ __forceinline__ void ldsm4(uint32_t& r0, uint32_t& r1, uint32_t& r2,
                                      uint32_t& r3, uint32_t addr) {
    asm volatile("ldmatrix.sync.aligned.m8n8.x4.shared.b16 {%0,%1,%2,%3}, [%4];"
                 : "=r"(r0), "=r"(r1), "=r"(r2), "=r"(r3) : "r"(addr));
}

#define NSTAGE 4
#define STG_B 20480
#define DYN_SMEM (NSTAGE * STG_B)   // 81920

// ---------------- tf32 GEMM: u(split, NN-B) + gh(plain TN) + conv job ------
__global__ __launch_bounds__(256, 2) void gemm_mma(Jobs jobs)
{
    gdc_launch();
    const int z = blockIdx.z;
    const int splitm = jobs.split[z];

    // ---- conversion job: fp32 -> fp16 weights/hidden + preW repack ----
    if (splitm == 2) {
        gdc_wait();
        const int c = blockIdx.y * gridDim.x + blockIdx.x;   // 0..95
        const int tid = threadIdx.x;
        const int total = 4 * W4 + (2 * NBNH) / 4;           // 3,407,872 float4
        for (int e = c * 256 + tid; e < total; e += 96 * 256) {
            const float* src; __half* dst; int le;
            if (e < W4)          { src = jobs.cWih0; dst = g_Wih0h; le = e; }
            else if (e < 2 * W4) { src = jobs.cWhh0; dst = (__half*)nullptr; le = e - W4; }
            else if (e < 3 * W4) { src = jobs.cWih1; dst = g_Wih1h; le = e - 2 * W4; }
            else if (e < 4 * W4) { src = jobs.cWhh1; dst = (__half*)nullptr; le = e - 3 * W4; }
            else                 { src = jobs.cHL;   dst = g_hLh;   le = e - 4 * W4; }
            if (!dst) continue;   // Whh stay fp32 (tf32 path)
            float4 v = ((const float4*)src)[le];
            __half2* d2 = (__half2*)dst + (size_t)le * 2;
            d2[0] = __floats2half2_rn(v.x, v.y);
            d2[1] = __floats2half2_rn(v.z, v.w);
        }
        for (int n = c; n < NH; n += 96) {
            for (int k = tid; k < CAT_LD; k += 256)
                g_preWh[(size_t)n * CAT_LD + k] =
                    (k < NH + NM)
                        ? __float2half(jobs.cPreW[(size_t)n * (NH + NM) + k])
                        : __half(0.f);
        }
        return;
    }

    if (blockIdx.x >= jobs.nx[z]) { gdc_wait(); return; }

    extern __shared__ float dyn[];
    __shared__ float bias_s[128];

    const float* A = jobs.A[z];
    const float* B = jobs.B[z];
    const float* bias = jobs.bias[z];
    float* C = jobs.C[z];
    const int lda = jobs.lda[z], ldb = jobs.ldb[z], ldc = jobs.ldc[z];
    const int nchunk = jobs.nchunk[z];
    const int nnflag = jobs.nn[z];

    const int tid = threadIdx.x;
    const int wid = tid >> 5, lane = tid & 31;
    const int g = lane >> 2, tg = lane & 3;
    const int wm = wid >> 2, wn = wid & 3;
    const int lq = lane >> 3, lr = lane & 7;
    const int n0 = blockIdx.x * 128;
    const int m0 = blockIdx.y * 128;

    if (tid < 128) bias_s[tid] = bias ? bias[n0 + tid] : 0.f;

    const uint32_t smem_base = smem_u32(dyn);
    const uint32_t a_off = (uint32_t)(((wm * 64 + (lq & 1) * 8 + lr) * 20 +
                                      (lq >> 1) * 4) * 4);
    const uint32_t b_off = (uint32_t)((2560 + (wn * 32 + (lq >> 1) * 8 + lr) * 20 +
                                      (lq & 1) * 4) * 4);
    const int lr0 = tid >> 2,          lk0 = tid & 3;
    const int lr1 = (tid + 256) >> 2,  lk1 = (tid + 256) & 3;

    auto load_chunk = [&](int cc, int s) {
        const uint32_t sa = smem_base + s * STG_B;
        const float* Ag = A + (size_t)m0 * lda + cc * 16;
        cp16(sa + (lr0 * 20 + lk0 * 4) * 4, Ag + (size_t)lr0 * lda + lk0 * 4);
        cp16(sa + (lr1 * 20 + lk1 * 4) * 4, Ag + (size_t)lr1 * lda + lk1 * 4);
        if (!nnflag) {
            const uint32_t sb = sa + 10240;
            const float* Bg = B + (size_t)n0 * ldb + cc * 16;
            cp16(sb + (lr0 * 20 + lk0 * 4) * 4, Bg + (size_t)lr0 * ldb + lk0 * 4);
            cp16(sb + (lr1 * 20 + lk1 * 4) * 4, Bg + (size_t)lr1 * ldb + lk1 * 4);
            asm volatile("cp.async.commit_group;" ::: "memory");
        } else {
            asm volatile("cp.async.commit_group;" ::: "memory");
            // B is [K,N] row-major: transpose into Bs[n][k] (stride 20)
            float* Bs = dyn + s * (STG_B / 4) + 2560;
#pragma unroll
            for (int q = 0; q < 2; q++) {
                const int f = tid * 2 + q;
                const int k = f >> 5, n4 = (f & 31) * 4;
                float4 v = *(const float4*)(B + (size_t)(cc * 16 + k) * ldb +
                                            n0 + n4);
                Bs[(n4 + 0) * 20 + k] = v.x;
                Bs[(n4 + 1) * 20 + k] = v.y;
                Bs[(n4 + 2) * 20 + k] = v.z;
                Bs[(n4 + 3) * 20 + k] = v.w;
            }
        }
    };

    float acc[4][4][4];
#pragma unroll
    for (int mt = 0; mt < 4; mt++)
#pragma unroll
        for (int nt = 0; nt < 4; nt++)
#pragma unroll
            for (int q = 0; q < 4; q++) acc[mt][nt][q] = 0.f;

    gdc_wait();
    load_chunk(0, 0); load_chunk(1, 1); load_chunk(2, 2);

    for (int t = 0; t < nchunk; t++) {
        if (t < nchunk - 2)
            asm volatile("cp.async.wait_group 2;" ::: "memory");
        else if (t == nchunk - 2)
            asm volatile("cp.async.wait_group 1;" ::: "memory");
        else
            asm volatile("cp.async.wait_group 0;" ::: "memory");
        __syncthreads();
        if (t + 3 < nchunk) load_chunk(t + 3, (t + 3) & 3);

        const uint32_t sbase = smem_base + (t & 3) * STG_B;
        const uint32_t abase = sbase + a_off;
        const uint32_t bbase = sbase + b_off;

#pragma unroll
        for (int ks = 0; ks < 2; ks++) {
            uint32_t au[4][4], bu[4][2];
#pragma unroll
            for (int mt = 0; mt < 4; mt++)
                ldsm4(au[mt][0], au[mt][1], au[mt][2], au[mt][3],
                      abase + mt * 1280 + ks * 32);
#pragma unroll
            for (int j = 0; j < 2; j++)
                ldsm4(bu[2 * j][0], bu[2 * j][1], bu[2 * j + 1][0],
                      bu[2 * j + 1][1], bbase + j * 1280 + ks * 32);

            if (!splitm) {
#pragma unroll
                for (int mt = 0; mt < 4; mt++)
#pragma unroll
                    for (int nt = 0; nt < 4; nt++)
                        mma_tf32(acc[mt][nt], au[mt][0], au[mt][1], au[mt][2],
                                 au[mt][3], bu[nt][0], bu[nt][1]);
            } else {
                uint32_t bh[4][2], bl[4][2];
#pragma unroll
                for (int nt = 0; nt < 4; nt++)
#pragma unroll
                    for (int q = 0; q < 2; q++) {
                        float v = __uint_as_float(bu[nt][q]);
                        uint32_t hi = tf32_rna(v);
                        bh[nt][q] = hi;
                        bl[nt][q] = tf32_rna(v - __uint_as_float(hi));
                    }
#pragma unroll
                for (int mt = 0; mt < 4; mt++) {
                    uint32_t ah[4], al[4];
#pragma unroll
                    for (int q = 0; q < 4; q++) {
                        float v = __uint_as_float(au[mt][q]);
                        ah[q] = tf32_rna(v);
                        al[q] = tf32_rna(v - __uint_as_float(ah[q]));
                    }
#pragma unroll
                    for (int nt = 0; nt < 4; nt++) {
                        mma_tf32(acc[mt][nt], al[0], al[1], al[2], al[3],
                                 bh[nt][0], bh[nt][1]);
                        mma_tf32(acc[mt][nt], ah[0], ah[1], ah[2], ah[3],
                                 bl[nt][0], bl[nt][1]);
                        mma_tf32(acc[mt][nt], ah[0], ah[1], ah[2], ah[3],
                                 bh[nt][0], bh[nt][1]);
                    }
                }
            }
        }
    }

#pragma unroll
    for (int mt = 0; mt < 4; mt++) {
        const int row = m0 + wm * 64 + mt * 16 + g;
        float* Cr0 = C + (size_t)row * ldc + n0;
        float* Cr1 = Cr0 + 8 * ldc;
#pragma unroll
        for (int nt = 0; nt < 4; nt++) {
            const int col = wn * 32 + nt * 8 + tg * 2;
            float2 v0 = make_float2(acc[mt][nt][0] + bias_s[col],
                                    acc[mt][nt][1] + bias_s[col + 1]);
            float2 v1 = make_float2(acc[mt][nt][2] + bias_s[col],
                                    acc[mt][nt][3] + bias_s[col + 1]);
            *(float2*)(Cr0 + col) = v0;
            *(float2*)(Cr1 + col) = v1;
        }
    }
}

// ---------------- fp16 GEMM ---------------------------------------------------
__global__ __launch_bounds__(256, 2) void gemm_h16(JobsH jobs)
{
    gdc_launch();
    const int z = blockIdx.z;
    if (blockIdx.x >= jobs.nx[z]) { gdc_wait(); return; }

    extern __shared__ float dyn[];
    __shared__ float bias_s[128];

    const __half* A = jobs.A[z];
    const __half* B = jobs.B[z];
    const float* bias = jobs.bias[z];
    float* C = jobs.C[z];
    const int lda = jobs.lda[z], ldb = jobs.ldb[z], ldc = jobs.ldc[z];
    const int nchunk = jobs.nchunk[z];

    const int tid = threadIdx.x;
    const int wid = tid >> 5, lane = tid & 31;
    const int g = lane >> 2, tg = lane & 3;
    const int wm = wid >> 2, wn = wid & 3;
    const int n0 = blockIdx.x * 128;
    const int m0 = blockIdx.y * 128;

    if (tid < 128) bias_s[tid] = bias ? bias[n0 + tid] : 0.f;

    const uint32_t smem_base = smem_u32(dyn);
    const uint32_t a_off = (uint32_t)(((wm * 64 + (lane & 15)) * 40 +
                                       (lane >> 4) * 8) * 2);
    const uint32_t b_off = (uint32_t)(10240 +
        ((wn * 32 + (lane & 7) + ((lane >> 4) << 3)) * 40 +
         ((lane >> 3) & 1) * 8) * 2);

    const int lr0 = tid >> 1;
    const int sg0 = (tid & 1) * 2;

    auto load_chunk = [&](int c, int s) {
        const uint32_t sa = smem_base + s * STG_B;
        const uint32_t sb = sa + 10240;
        const __half* Ag = A + (size_t)m0 * lda + c * 32;
        const __half* Bg = B + (size_t)n0 * ldb + c * 32;
#pragma unroll
        for (int q = 0; q < 2; q++) {
            const int sg = sg0 + q;
            cp16(sa + (lr0 * 40 + sg * 8) * 2, Ag + (size_t)lr0 * lda + sg * 8);
            cp16(sb + (lr0 * 40 + sg * 8) * 2, Bg + (size_t)lr0 * ldb + sg * 8);
        }
        asm volatile("cp.async.commit_group;" ::: "memory");
    };

    float acc[4][4][4];
#pragma unroll
    for (int mt = 0; mt < 4; mt++)
#pragma unroll
        for (int nt = 0; nt < 4; nt++)
#pragma unroll
            for (int q = 0; q < 4; q++) acc[mt][nt][q] = 0.f;

    gdc_wait();
    load_chunk(0, 0);
    if (nchunk > 1) load_chunk(1, 1);
    if (nchunk > 2) load_chunk(2, 2);

    for (int t = 0; t < nchunk; t++) {
        if (t < nchunk - 2)
            asm volatile("cp.async.wait_group 2;" ::: "memory");
        else if (t == nchunk - 2)
            asm volatile("cp.async.wait_group 1;" ::: "memory");
        else
            asm volatile("cp.async.wait_group 0;" ::: "memory");
        __syncthreads();
        if (t + 3 < nchunk) load_chunk(t + 3, (t + 3) & 3);

        const uint32_t sbase = smem_base + (t & 3) * STG_B;
        const uint32_t abase = sbase + a_off;
        const uint32_t bbase = sbase + b_off;

#pragma unroll
        for (int ks = 0; ks < 2; ks++) {
            uint32_t au[4][4], bu[4][2];
#pragma unroll
            for (int mt = 0; mt < 4; mt++)
                ldsm4(au[mt][0], au[mt][1], au[mt][2], au[mt][3],
                      abase + mt * 1280 + ks * 32);
#pragma unroll
            for (int j = 0; j < 2; j++)
                ldsm4(bu[2 * j][0], bu[2 * j][1], bu[2 * j + 1][0],
                      bu[2 * j + 1][1], bbase + j * 1280 + ks * 32);
#pragma unroll
            for (int mt = 0; mt < 4; mt++)
#pragma unroll
                for (int nt = 0; nt < 4; nt++)
                    mma_f16(acc[mt][nt], au[mt][0], au[mt][1], au[mt][2],
                            au[mt][3], bu[nt][0], bu[nt][1]);
        }
    }

#pragma unroll
    for (int mt = 0; mt < 4; mt++) {
        const int row = m0 + wm * 64 + mt * 16 + g;
        float* Cr0 = C + (size_t)row * ldc + n0;
        float* Cr1 = Cr0 + 8 * ldc;
#pragma unroll
        for (int nt = 0; nt < 4; nt++) {
            const int col = wn * 32 + nt * 8 + tg * 2;
            float2 v0 = make_float2(acc[mt][nt][0] + bias_s[col],
                                    acc[mt][nt][1] + bias_s[col + 1]);
            float2 v1 = make_float2(acc[mt][nt][2] + bias_s[col],
                                    acc[mt][nt][3] + bias_s[col + 1]);
            *(float2*)(Cr0 + col) = v0;
            *(float2*)(Cr1 + col) = v1;
        }
    }
}

__device__ __forceinline__ float warp_sum(float v) {
#pragma unroll
    for (int o = 16; o; o >>= 1) v += __shfl_xor_sync(0xffffffffu, v, o);
    return v;
}

// ---------------- fused attention: 8-way u-reduce + online softmax ----------
__global__ __launch_bounds__(256, 3) void attn_fused(
    const float* __restrict__ enc, const float* __restrict__ upart,
    const float* __restrict__ motion, float* __restrict__ attn_out,
    __half* __restrict__ cath)
{
    gdc_launch();
    const int b = blockIdx.x;
    const int tid = threadIdx.x;
    const int lane = tid & 31, w = tid >> 5;

    __shared__ float e_raw[NS];
    __shared__ float warp_m[8], warp_z[8];
    __shared__ __align__(16) float ur_s[NH];
    __shared__ __align__(16) float ctxs[8 * NH];

    gdc_wait();
    {
        float4 v = make_float4(0.f, 0.f, 0.f, 0.f);
#pragma unroll
        for (int s = 0; s < 8; s++) {
            float4 p = ((const float4*)(upart + (size_t)s * NBNH +
                                        (size_t)b * NH))[tid];
            v.x += p.x; v.y += p.y; v.z += p.z; v.w += p.w;
        }
        ((float4*)ur_s)[tid] = v;
    }
    __syncthreads();

    float4 cacc[8];
#pragma unroll
    for (int i = 0; i < 8; i++) cacc[i] = make_float4(0.f, 0.f, 0.f, 0.f);
    float m = -1e30f, Z = 0.f;
    const float4* u4 = (const float4*)ur_s;

#pragma unroll
    for (int si = 0; si < 8; si++) {
        const int s = w + si * 8;
        const float4* ep = (const float4*)(enc + ((size_t)s * NB + b) * NH);
        float4 row[8];
        float d = 0.f;
#pragma unroll
        for (int i = 0; i < 8; i++) {
            row[i] = ep[i * 32 + lane];
            float4 uv = u4[i * 32 + lane];
            d = fmaf(row[i].x, uv.x, d);
            d = fmaf(row[i].y, uv.y, d);
            d = fmaf(row[i].z, uv.z, d);
            d = fmaf(row[i].w, uv.w, d);
        }
        d = warp_sum(d);
        if (lane == 0) e_raw[s] = d;
        const float mn = fmaxf(m, d);
        const float scale = __expf(m - mn);
        const float wgt = __expf(d - mn);
        Z = Z * scale + wgt;
#pragma unroll
        for (int i = 0; i < 8; i++) {
            cacc[i].x = fmaf(cacc[i].x, scale, wgt * row[i].x);
            cacc[i].y = fmaf(cacc[i].y, scale, wgt * row[i].y);
            cacc[i].z = fmaf(cacc[i].z, scale, wgt * row[i].z);
            cacc[i].w = fmaf(cacc[i].w, scale, wgt * row[i].w);
        }
        m = mn;
    }

    if (lane == 0) { warp_m[w] = m; warp_z[w] = Z; }
    float4* cs = (float4*)(ctxs + w * NH);
#pragma unroll
    for (int i = 0; i < 8; i++) cs[i * 32 + lane] = cacc[i];
    __syncthreads();

    float gm = warp_m[0];
#pragma unroll
    for (int ww = 1; ww < 8; ww++) gm = fmaxf(gm, warp_m[ww]);
    float gZ = 0.f;
#pragma unroll
    for (int ww = 0; ww < 8; ww++) gZ += warp_z[ww] * __expf(warp_m[ww] - gm);
    const float invZ = 1.f / gZ;

    if (tid < NS) attn_out[(size_t)b * NS + tid] = __expf(e_raw[tid] - gm) * invZ;
    if (tid < NM)
        cath[(size_t)b * CAT_LD + tid] = __float2half(motion[(size_t)b * NM + tid]);
    if (tid < CAT_LD - NH - NM)
        cath[(size_t)b * CAT_LD + NH + NM + tid] = __half(0.f);

    float4 a = make_float4(0.f, 0.f, 0.f, 0.f);
#pragma unroll
    for (int ww = 0; ww < 8; ww++) {
        const float sc = __expf(warp_m[ww] - gm);
        float4 v = *(const float4*)&ctxs[ww * NH + tid * 4];
        a.x = fmaf(v.x, sc, a.x);
        a.y = fmaf(v.y, sc, a.y);
        a.z = fmaf(v.z, sc, a.z);
        a.w = fmaf(v.w, sc, a.w);
    }
    __half* cp = cath + (size_t)b * CAT_LD + NM + tid * 4;
    *(__half2*)cp       = __floats2half2_rn(a.x * invZ, a.y * invZ);
    *(__half2*)(cp + 2) = __floats2half2_rn(a.z * invZ, a.w * invZ);
}

// ---------------- x0 split-K reduce (6 partials) -> fp16 --------------------
__global__ __launch_bounds__(256) void xreduce(const float* __restrict__ p,
                                               __half* __restrict__ x0h)
{
    gdc_launch();
    gdc_wait();
    const int i = (blockIdx.x * 256 + threadIdx.x) * 4;
    float4 v = *(const float4*)(p + i);
#pragma unroll
    for (int s = 1; s < 6; s++) {
        float4 w = *(const float4*)(p + (size_t)s * NBNH + i);
        v.x += w.x; v.y += w.y; v.z += w.z; v.w += w.w;
    }
    *(__half2*)(x0h + i)     = __floats2half2_rn(v.x, v.y);
    *(__half2*)(x0h + i + 2) = __floats2half2_rn(v.z, v.w);
}

// ---------------- GRU gate pointwise (layer 0, 2-way split gi) --------------
__global__ __launch_bounds__(256) void gate_kernel(
    const float* __restrict__ giA, const float* __restrict__ giB,
    const float* __restrict__ gh, const float* __restrict__ hprev,
    float* __restrict__ out_h, __half* __restrict__ out_h16)
{
    gdc_launch();
    gdc_wait();
    const int idx = blockIdx.x * blockDim.x + threadIdx.x;
    const int b = idx >> 10, n = idx & (NH - 1);
    const size_t o = (size_t)b * G3 + n;
    float ir = giA[o] + giB[o];
    float iz = giA[o + NH] + giB[o + NH];
    float inn = giA[o + 2 * NH] + giB[o + 2 * NH];
    float hr = gh[o], hz = gh[o + NH], hn = gh[o + 2 * NH];
    float r = 1.f / (1.f + expf(-(ir + hr)));
    float z = 1.f / (1.f + expf(-(iz + hz)));
    float nn = tanhf(inn + r * hn);
    float h = (1.f - z) * nn + z * hprev[idx];
    out_h[idx] = h;
    out_h16[idx] = __float2half(h);
}

// ---------------- fused gate(layer 1, 3-way split-K gi) + post linear -------
__global__ __launch_bounds__(256) void gatepost_kernel(
    const float* __restrict__ giA, const float* __restrict__ giB,
    const float* __restrict__ giC, const float* __restrict__ gh,
    const float* __restrict__ hprev, float* __restrict__ out_h,
    const float* __restrict__ W, const float* __restrict__ bias,
    float* __restrict__ out)
{
    gdc_launch();
    gdc_wait();
    const int b = blockIdx.x;
    const int tid = threadIdx.x;

    float hv[4];
#pragma unroll
    for (int q = 0; q < 4; q++) {
        const int n = tid * 4 + q;
        const size_t o = (size_t)b * G3 + n;
        float ir = giA[o] + giB[o] + giC[o];
        float iz = giA[o + NH] + giB[o + NH] + giC[o + NH];
        float inn = giA[o + 2 * NH] + giB[o + 2 * NH] + giC[o + 2 * NH];
        float hr = gh[o], hz = gh[o + NH], hn = gh[o + 2 * NH];
        float r = 1.f / (1.f + expf(-(ir + hr)));
        float z = 1.f / (1.f + expf(-(iz + hz)));
        float nn = tanhf(inn + r * hn);
        hv[q] = (1.f - z) * nn + z * hprev[(size_t)b * NH + n];
    }
    *(float4*)(out_h + (size_t)b * NH + tid * 4) =
        make_float4(hv[0], hv[1], hv[2], hv[3]);

    float acc[10];
#pragma unroll
    for (int o = 0; o < 10; o++) {
        const float4 wv = *(const float4*)(W + (size_t)o * NH + tid * 4);
        acc[o] = hv[0] * wv.x + hv[1] * wv.y + hv[2] * wv.z + hv[3] * wv.w;
    }
    __shared__ float red[10][8];
    const int lane = tid & 31, w = tid >> 5;
#pragma unroll
    for (int o = 0; o < 10; o++) {
        float v = warp_sum(acc[o]);
        if (lane == 0) red[o][w] = v;
    }
    __syncthreads();
    if (tid < 10) {
        float s = 0.f;
#pragma unroll
        for (int ww = 0; ww < 8; ww++) s += red[tid][ww];
        out[(size_t)b * 10 + tid] = s + bias[tid];
    }
}

// ---------------- host launch ------------------------------------------------
template <typename F, typename... Args>
static void pdl_launch(F kern, dim3 grid, dim3 block, size_t smem,
                       Args... args)
{
    cudaLaunchConfig_t cfg = {};
    cfg.gridDim = grid;
    cfg.blockDim = block;
    cfg.dynamicSmemBytes = smem;
    cfg.stream = 0;
    cudaLaunchAttribute at[1];
    at[0].id = cudaLaunchAttributeProgrammaticStreamSerialization;
    at[0].val.programmaticStreamSerializationAllowed = 1;
    cfg.attrs = at;
    cfg.numAttrs = 1;
    cudaLaunchKernelEx(&cfg, kern, args...);
}

extern "C" void kernel_launch(void* const* d_in, const int* in_sizes, int n_in,
                              void* d_out, int out_size)
{
    const float* motion      = (const float*)d_in[0];
    const float* last_hidden = (const float*)d_in[1];
    const float* enc         = (const float*)d_in[2];
    const float* attn_W      = (const float*)d_in[3];
    /* d_in[4] = attn_b: unused (softmax shift-invariant) */
    const float* pre_W  = (const float*)d_in[5];
    const float* pre_b  = (const float*)d_in[6];
    const float* Wih0   = (const float*)d_in[7];
    const float* Whh0   = (const float*)d_in[8];
    const float* bih0   = (const float*)d_in[9];
    const float* bhh0   = (const float*)d_in[10];
    const float* Wih1   = (const float*)d_in[11];
    const float* Whh1   = (const float*)d_in[12];
    const float* bih1   = (const float*)d_in[13];
    const float* bhh1   = (const float*)d_in[14];
    const float* post_W = (const float*)d_in[15];
    const float* post_b = (const float*)d_in[16];

    float* out        = (float*)d_out;
    float* out_output = out;
    float* out_h0     = out + NB * 10;
    float* out_h1     = out + NB * 10 + NBNH;
    float* out_attn   = out + NB * 10 + 2 * NBNH;

    float *upart, *xpart, *gi0A, *gi0B, *gh0, *gh1, *gi1A, *gi1B, *gi1C;
    __half *preWh, *Wih0h, *Wih1h, *hLh, *cath, *x0h, *h0h;
    cudaGetSymbolAddress((void**)&upart, g_upart);
    cudaGetSymbolAddress((void**)&xpart, g_xpart);
    cudaGetSymbolAddress((void**)&gi0A,  g_gi0A);
    cudaGetSymbolAddress((void**)&gi0B,  g_gi0B);
    cudaGetSymbolAddress((void**)&gh0,   g_gh0);
    cudaGetSymbolAddress((void**)&gh1,   g_gh1);
    cudaGetSymbolAddress((void**)&gi1A,  g_gi1A);
    cudaGetSymbolAddress((void**)&gi1B,  g_gi1B);
    cudaGetSymbolAddress((void**)&gi1C,  g_gi1C);
    cudaGetSymbolAddress((void**)&preWh, g_preWh);
    cudaGetSymbolAddress((void**)&Wih0h, g_Wih0h);
    cudaGetSymbolAddress((void**)&Wih1h, g_Wih1h);
    cudaGetSymbolAddress((void**)&hLh,   g_hLh);
    cudaGetSymbolAddress((void**)&cath,  g_cath);
    cudaGetSymbolAddress((void**)&x0h,   g_x0h);
    cudaGetSymbolAddress((void**)&h0h,   g_h0h);

    const float* hL0 = last_hidden;
    const float* hL1 = last_hidden + NBNH;
    const __half* hL0h = hLh;
    const __half* hL1h = hLh + NBNH;

    cudaFuncSetAttribute(gemm_mma, cudaFuncAttributeMaxDynamicSharedMemorySize,
                         DYN_SMEM);
    cudaFuncSetAttribute(gemm_h16, cudaFuncAttributeMaxDynamicSharedMemorySize,
                         DYN_SMEM);

    // 1) MEGA launch 1: u split-K x8 (split-tf32, NN-B) + gh0 + gh1 (tf32)
    //    + fp16 conversion job. All jobs independent, read only raw inputs.
    {
        Jobs j = {};
        for (int s = 0; s < 8; s++) {
            j.A[s] = hL1 + s * 128;
            j.B[s] = attn_W + (size_t)s * 128 * NH;   // NN: rows k', cols h
            j.bias[s] = nullptr; j.C[s] = upart + (size_t)s * NBNH;
            j.lda[s] = NH; j.ldb[s] = NH; j.ldc[s] = NH;
            j.nchunk[s] = 8; j.nx[s] = 8; j.split[s] = 1; j.nn[s] = 1;
        }
        j.A[8] = hL0; j.B[8] = Whh0; j.bias[8] = bhh0; j.C[8] = gh0;
        j.A[9] = hL1; j.B[9] = Whh1; j.bias[9] = bhh1; j.C[9] = gh1;
        for (int s = 8; s < 10; s++) {
            j.lda[s] = NH; j.ldb[s] = NH; j.ldc[s] = G3;
            j.nchunk[s] = 64; j.nx[s] = 24; j.split[s] = 0; j.nn[s] = 0;
        }
        j.split[10] = 2; j.nx[10] = 24;                  // conversion job
        j.cWih0 = Wih0; j.cWhh0 = Whh0; j.cWih1 = Wih1; j.cWhh1 = Whh1;
        j.cHL = last_hidden; j.cPreW = pre_W;
        gemm_mma<<<dim3(24, 4, 11), 256, DYN_SMEM>>>(j);
    }

    // 2) fused attention — PDL
    pdl_launch(attn_fused, dim3(NB), dim3(256), 0,
               enc, (const float*)upart, motion, out_attn, cath);

    // 3) pre split-K x6 — PDL
    {
        JobsH j = {};
        const int koff[6] = {0, 192, 384, 576, 736, 896};
        const int nch[6]  = {6, 6, 6, 5, 5, 5};
        for (int s = 0; s < 6; s++) {
            j.A[s] = cath + koff[s]; j.B[s] = preWh + koff[s];
            j.bias[s] = (s == 0) ? pre_b : nullptr;
            j.C[s] = xpart + (size_t)s * NBNH;
            j.lda[s] = CAT_LD; j.ldb[s] = CAT_LD; j.ldc[s] = NH;
            j.nchunk[s] = nch[s]; j.nx[s] = 8;
        }
        pdl_launch(gemm_h16, dim3(8, 4, 6), dim3(256), DYN_SMEM, j);
    }
    pdl_launch(xreduce, dim3(NBNH / 1024), dim3(256), 0,
               (const float*)xpart, x0h);

    // 4) gi0 split-K x2 (fp16) — PDL
    {
        JobsH j = {};
        for (int k = 0; k < 2; k++) {
            j.A[k] = x0h + k * 512; j.B[k] = Wih0h + k * 512;
            j.bias[k] = k ? nullptr : bih0;
            j.C[k] = k ? gi0B : gi0A;
            j.lda[k] = NH; j.ldb[k] = NH; j.ldc[k] = G3;
            j.nchunk[k] = 16; j.nx[k] = 24;
        }
        pdl_launch(gemm_h16, dim3(24, 4, 2), dim3(256), DYN_SMEM, j);
    }

    // 5) gate0 — PDL
    pdl_launch(gate_kernel, dim3(NBNH / 256), dim3(256), 0,
               (const float*)gi0A, (const float*)gi0B, (const float*)gh0,
               last_hidden, out_h0, h0h);

    // 6) gi1 split-K x3 (fp16) — PDL
    {
        JobsH j = {};
        const int koff[3] = {0, 352, 704};
        const int nch[3] = {11, 11, 10};
        float* dst[3] = {gi1A, gi1B, gi1C};
        for (int k = 0; k < 3; k++) {
            j.A[k] = h0h + koff[k]; j.B[k] = Wih1h + koff[k];
            j.bias[k] = k ? nullptr : bih1;
            j.C[k] = dst[k];
            j.lda[k] = NH; j.ldb[k] = NH; j.ldc[k] = G3;
            j.nchunk[k] = nch[k]; j.nx[k] = 24;
        }
        pdl_launch(gemm_h16, dim3(24, 4, 3), dim3(256), DYN_SMEM, j);
    }

    // 7) gate1 + post — PDL
    pdl_launch(gatepost_kernel, dim3(NB), dim3(256), 0,
               (const float*)gi1A, (const float*)gi1B, (const float*)gi1C,
               (const float*)gh1, hL1, out_h1, post_W, post_b, out_output);
}

// round 15
// speedup vs baseline: 1.3198x; 1.3198x over previous
#include <cuda_runtime.h>
#include <cuda_fp16.h>
#include <math.h>
#include <stdint.h>

#define NB 512
#define NH 1024
#define NS 64
#define NM 10
#define CAT_LD 1056
#define NBNH (NB * NH)
#define G3 (3 * NH)
#define NJOBS 8
#define W4 786432                     // G3*NH/4

// ---------------- scratch (device globals) ----------------------------------
__device__ __align__(1024) float  g_Wt[NH * NH];
__device__ __align__(1024) __half g_preWh[NH * CAT_LD];
__device__ __align__(1024) __half g_Wih0h[G3 * NH];
__device__ __align__(1024) __half g_Whh0h[G3 * NH];
__device__ __align__(1024) __half g_Wih1h[G3 * NH];
__device__ __align__(1024) __half g_Whh1h[G3 * NH];
__device__ __align__(1024) __half g_hLh[2 * NBNH];
__device__ __align__(1024) float  g_upart[8 * NBNH];
__device__ __align__(1024) __half g_cath[NB * CAT_LD];
__device__ __align__(1024) float  g_xpart[6 * NBNH];
__device__ __align__(1024) __half g_x0h[NBNH];
__device__ __align__(1024) __half g_h0h[NBNH];
__device__ __align__(1024) float  g_gi0A[NB * G3];
__device__ __align__(1024) float  g_gi0B[NB * G3];
__device__ __align__(1024) float  g_gi0C[NB * G3];
__device__ __align__(1024) float  g_gh0[NB * G3];
__device__ __align__(1024) float  g_gh1[NB * G3];
__device__ __align__(1024) float  g_gi1A[NB * G3];
__device__ __align__(1024) float  g_gi1B[NB * G3];
__device__ __align__(1024) float  g_gi1C[NB * G3];

struct Jobs {
    const float* A[NJOBS]; const float* B[NJOBS];
    const float* bias[NJOBS]; float* C[NJOBS];
    int lda[NJOBS], ldb[NJOBS], ldc[NJOBS], nchunk[NJOBS], nx[NJOBS], split[NJOBS];
};
struct JobsH {
    const __half* A[NJOBS]; const __half* B[NJOBS];
    const float* bias[NJOBS]; float* C[NJOBS];
    int lda[NJOBS], ldb[NJOBS], ldc[NJOBS], nchunk[NJOBS], nx[NJOBS];
};

// ---------------- helpers ----------------------------------------------------
__device__ __forceinline__ void gdc_launch() {
    asm volatile("griddepcontrol.launch_dependents;" ::: "memory");
}
__device__ __forceinline__ void gdc_wait() {
    asm volatile("griddepcontrol.wait;" ::: "memory");
}
__device__ __forceinline__ uint32_t smem_u32(const void* p) {
    uint32_t a;
    asm("{ .reg .u64 t; cvta.to.shared.u64 t, %1; cvt.u32.u64 %0, t; }"
        : "=r"(a) : "l"(p));
    return a;
}
__device__ __forceinline__ uint32_t tf32_rna(float x) {
    uint32_t r;
    asm("cvt.rna.tf32.f32 %0, %1;" : "=r"(r) : "f"(x));
    return r;
}
__device__ __forceinline__ void mma_tf32(float* c, uint32_t a0, uint32_t a1,
                                         uint32_t a2, uint32_t a3,
                                         uint32_t b0, uint32_t b1) {
    asm volatile(
        "mma.sync.aligned.m16n8k8.row.col.f32.tf32.tf32.f32 "
        "{%0,%1,%2,%3}, {%4,%5,%6,%7}, {%8,%9}, {%0,%1,%2,%3};"
        : "+f"(c[0]), "+f"(c[1]), "+f"(c[2]), "+f"(c[3])
        : "r"(a0), "r"(a1), "r"(a2), "r"(a3), "r"(b0), "r"(b1));
}
__device__ __forceinline__ void mma_f16(float* c, uint32_t a0, uint32_t a1,
                                        uint32_t a2, uint32_t a3,
                                        uint32_t b0, uint32_t b1) {
    asm volatile(
        "mma.sync.aligned.m16n8k16.row.col.f32.f16.f16.f32 "
        "{%0,%1,%2,%3}, {%4,%5,%6,%7}, {%8,%9}, {%0,%1,%2,%3};"
        : "+f"(c[0]), "+f"(c[1]), "+f"(c[2]), "+f"(c[3])
        : "r"(a0), "r"(a1), "r"(a2), "r"(a3), "r"(b0), "r"(b1));
}
__device__ __forceinline__ void cp16(uint32_t dst, const void* src) {
    asm volatile("cp.async.cg.shared.global [%0], [%1], 16;"
                 :: "r"(dst), "l"(src));
}
__device__ __forceinline__ void ldsm4(uint32_t& r0, uint32_t& r1, uint32_t& r2,
                                      uint32_t& r3, uint32_t addr) {
    asm volatile("ldmatrix.sync.aligned.m8n8.x4.shared.b16 {%0,%1,%2,%3}, [%4];"
                 : "=r"(r0), "=r"(r1), "=r"(r2), "=r"(r3) : "r"(addr));
}

#define NSTAGE 4
#define STG_B 20480
#define DYN_SMEM (NSTAGE * STG_B)   // 81920

// ---------------- tf32 GEMM (split path only: u) -----------------------------
__global__ __launch_bounds__(256, 2) void gemm_mma(Jobs jobs)
{
    gdc_launch();
    const int z = blockIdx.z;
    if (blockIdx.x >= jobs.nx[z]) { gdc_wait(); return; }

    extern __shared__ float dyn[];
    __shared__ float bias_s[128];

    const float* A = jobs.A[z];
    const float* B = jobs.B[z];
    const float* bias = jobs.bias[z];
    float* C = jobs.C[z];
    const int lda = jobs.lda[z], ldb = jobs.ldb[z], ldc = jobs.ldc[z];
    const int nchunk = jobs.nchunk[z], split = jobs.split[z];

    const int tid = threadIdx.x;
    const int wid = tid >> 5, lane = tid & 31;
    const int g = lane >> 2, tg = lane & 3;
    const int wm = wid >> 2, wn = wid & 3;
    const int lq = lane >> 3, lr = lane & 7;
    const int n0 = blockIdx.x * 128;
    const int m0 = blockIdx.y * 128;

    if (tid < 128) bias_s[tid] = bias ? bias[n0 + tid] : 0.f;

    const uint32_t smem_base = smem_u32(dyn);
    const uint32_t a_off = (uint32_t)(((wm * 64 + (lq & 1) * 8 + lr) * 20 +
                                      (lq >> 1) * 4) * 4);
    const uint32_t b_off = (uint32_t)((2560 + (wn * 32 + (lq >> 1) * 8 + lr) * 20 +
                                      (lq & 1) * 4) * 4);
    const int lr0 = tid >> 2,          lk0 = tid & 3;
    const int lr1 = (tid + 256) >> 2,  lk1 = (tid + 256) & 3;

    auto load_chunk = [&](int c, int s) {
        const uint32_t sa = smem_base + s * STG_B;
        const uint32_t sb = sa + 10240;
        const float* Ag = A + (size_t)m0 * lda + c * 16;
        const float* Bg = B + (size_t)n0 * ldb + c * 16;
        cp16(sa + (lr0 * 20 + lk0 * 4) * 4, Ag + (size_t)lr0 * lda + lk0 * 4);
        cp16(sa + (lr1 * 20 + lk1 * 4) * 4, Ag + (size_t)lr1 * lda + lk1 * 4);
        cp16(sb + (lr0 * 20 + lk0 * 4) * 4, Bg + (size_t)lr0 * ldb + lk0 * 4);
        cp16(sb + (lr1 * 20 + lk1 * 4) * 4, Bg + (size_t)lr1 * ldb + lk1 * 4);
        asm volatile("cp.async.commit_group;" ::: "memory");
    };

    float acc[4][4][4];
#pragma unroll
    for (int mt = 0; mt < 4; mt++)
#pragma unroll
        for (int nt = 0; nt < 4; nt++)
#pragma unroll
            for (int q = 0; q < 4; q++) acc[mt][nt][q] = 0.f;

    gdc_wait();
    load_chunk(0, 0); load_chunk(1, 1); load_chunk(2, 2);

    for (int t = 0; t < nchunk; t++) {
        if (t < nchunk - 2)
            asm volatile("cp.async.wait_group 2;" ::: "memory");
        else if (t == nchunk - 2)
            asm volatile("cp.async.wait_group 1;" ::: "memory");
        else
            asm volatile("cp.async.wait_group 0;" ::: "memory");
        __syncthreads();
        if (t + 3 < nchunk) load_chunk(t + 3, (t + 3) & 3);

        const uint32_t sbase = smem_base + (t & 3) * STG_B;
        const uint32_t abase = sbase + a_off;
        const uint32_t bbase = sbase + b_off;

#pragma unroll
        for (int ks = 0; ks < 2; ks++) {
            uint32_t au[4][4], bu[4][2];
#pragma unroll
            for (int mt = 0; mt < 4; mt++)
                ldsm4(au[mt][0], au[mt][1], au[mt][2], au[mt][3],
                      abase + mt * 1280 + ks * 32);
#pragma unroll
            for (int j = 0; j < 2; j++)
                ldsm4(bu[2 * j][0], bu[2 * j][1], bu[2 * j + 1][0],
                      bu[2 * j + 1][1], bbase + j * 1280 + ks * 32);

            if (!split) {
#pragma unroll
                for (int mt = 0; mt < 4; mt++)
#pragma unroll
                    for (int nt = 0; nt < 4; nt++)
                        mma_tf32(acc[mt][nt], au[mt][0], au[mt][1], au[mt][2],
                                 au[mt][3], bu[nt][0], bu[nt][1]);
            } else {
                uint32_t bh[4][2], bl[4][2];
#pragma unroll
                for (int nt = 0; nt < 4; nt++)
#pragma unroll
                    for (int q = 0; q < 2; q++) {
                        float v = __uint_as_float(bu[nt][q]);
                        uint32_t hi = tf32_rna(v);
                        bh[nt][q] = hi;
                        bl[nt][q] = tf32_rna(v - __uint_as_float(hi));
                    }
#pragma unroll
                for (int mt = 0; mt < 4; mt++) {
                    uint32_t ah[4], al[4];
#pragma unroll
                    for (int q = 0; q < 4; q++) {
                        float v = __uint_as_float(au[mt][q]);
                        ah[q] = tf32_rna(v);
                        al[q] = tf32_rna(v - __uint_as_float(ah[q]));
                    }
#pragma unroll
                    for (int nt = 0; nt < 4; nt++) {
                        mma_tf32(acc[mt][nt], al[0], al[1], al[2], al[3],
                                 bh[nt][0], bh[nt][1]);
                        mma_tf32(acc[mt][nt], ah[0], ah[1], ah[2], ah[3],
                                 bl[nt][0], bl[nt][1]);
                        mma_tf32(acc[mt][nt], ah[0], ah[1], ah[2], ah[3],
                                 bh[nt][0], bh[nt][1]);
                    }
                }
            }
        }
    }

#pragma unroll
    for (int mt = 0; mt < 4; mt++) {
        const int row = m0 + wm * 64 + mt * 16 + g;
        float* Cr0 = C + (size_t)row * ldc + n0;
        float* Cr1 = Cr0 + 8 * ldc;
#pragma unroll
        for (int nt = 0; nt < 4; nt++) {
            const int col = wn * 32 + nt * 8 + tg * 2;
            float2 v0 = make_float2(acc[mt][nt][0] + bias_s[col],
                                    acc[mt][nt][1] + bias_s[col + 1]);
            float2 v1 = make_float2(acc[mt][nt][2] + bias_s[col],
                                    acc[mt][nt][3] + bias_s[col + 1]);
            *(float2*)(Cr0 + col) = v0;
            *(float2*)(Cr1 + col) = v1;
        }
    }
}

// ---------------- fp16 GEMM ---------------------------------------------------
__global__ __launch_bounds__(256, 2) void gemm_h16(JobsH jobs)
{
    gdc_launch();
    const int z = blockIdx.z;
    if (blockIdx.x >= jobs.nx[z]) { gdc_wait(); return; }

    extern __shared__ float dyn[];
    __shared__ float bias_s[128];

    const __half* A = jobs.A[z];
    const __half* B = jobs.B[z];
    const float* bias = jobs.bias[z];
    float* C = jobs.C[z];
    const int lda = jobs.lda[z], ldb = jobs.ldb[z], ldc = jobs.ldc[z];
    const int nchunk = jobs.nchunk[z];

    const int tid = threadIdx.x;
    const int wid = tid >> 5, lane = tid & 31;
    const int g = lane >> 2, tg = lane & 3;
    const int wm = wid >> 2, wn = wid & 3;
    const int n0 = blockIdx.x * 128;
    const int m0 = blockIdx.y * 128;

    if (tid < 128) bias_s[tid] = bias ? bias[n0 + tid] : 0.f;

    const uint32_t smem_base = smem_u32(dyn);
    const uint32_t a_off = (uint32_t)(((wm * 64 + (lane & 15)) * 40 +
                                       (lane >> 4) * 8) * 2);
    const uint32_t b_off = (uint32_t)(10240 +
        ((wn * 32 + (lane & 7) + ((lane >> 4) << 3)) * 40 +
         ((lane >> 3) & 1) * 8) * 2);

    const int lr0 = tid >> 1;
    const int sg0 = (tid & 1) * 2;

    auto load_chunk = [&](int c, int s) {
        const uint32_t sa = smem_base + s * STG_B;
        const uint32_t sb = sa + 10240;
        const __half* Ag = A + (size_t)m0 * lda + c * 32;
        const __half* Bg = B + (size_t)n0 * ldb + c * 32;
#pragma unroll
        for (int q = 0; q < 2; q++) {
            const int sg = sg0 + q;
            cp16(sa + (lr0 * 40 + sg * 8) * 2, Ag + (size_t)lr0 * lda + sg * 8);
            cp16(sb + (lr0 * 40 + sg * 8) * 2, Bg + (size_t)lr0 * ldb + sg * 8);
        }
        asm volatile("cp.async.commit_group;" ::: "memory");
    };

    float acc[4][4][4];
#pragma unroll
    for (int mt = 0; mt < 4; mt++)
#pragma unroll
        for (int nt = 0; nt < 4; nt++)
#pragma unroll
            for (int q = 0; q < 4; q++) acc[mt][nt][q] = 0.f;

    gdc_wait();
    load_chunk(0, 0);
    if (nchunk > 1) load_chunk(1, 1);
    if (nchunk > 2) load_chunk(2, 2);

    for (int t = 0; t < nchunk; t++) {
        if (t < nchunk - 2)
            asm volatile("cp.async.wait_group 2;" ::: "memory");
        else if (t == nchunk - 2)
            asm volatile("cp.async.wait_group 1;" ::: "memory");
        else
            asm volatile("cp.async.wait_group 0;" ::: "memory");
        __syncthreads();
        if (t + 3 < nchunk) load_chunk(t + 3, (t + 3) & 3);

        const uint32_t sbase = smem_base + (t & 3) * STG_B;
        const uint32_t abase = sbase + a_off;
        const uint32_t bbase = sbase + b_off;

#pragma unroll
        for (int ks = 0; ks < 2; ks++) {
            uint32_t au[4][4], bu[4][2];
#pragma unroll
            for (int mt = 0; mt < 4; mt++)
                ldsm4(au[mt][0], au[mt][1], au[mt][2], au[mt][3],
                      abase + mt * 1280 + ks * 32);
#pragma unroll
            for (int j = 0; j < 2; j++)
                ldsm4(bu[2 * j][0], bu[2 * j][1], bu[2 * j + 1][0],
                      bu[2 * j + 1][1], bbase + j * 1280 + ks * 32);
#pragma unroll
            for (int mt = 0; mt < 4; mt++)
#pragma unroll
                for (int nt = 0; nt < 4; nt++)
                    mma_f16(acc[mt][nt], au[mt][0], au[mt][1], au[mt][2],
                            au[mt][3], bu[nt][0], bu[nt][1]);
        }
    }

#pragma unroll
    for (int mt = 0; mt < 4; mt++) {
        const int row = m0 + wm * 64 + mt * 16 + g;
        float* Cr0 = C + (size_t)row * ldc + n0;
        float* Cr1 = Cr0 + 8 * ldc;
#pragma unroll
        for (int nt = 0; nt < 4; nt++) {
            const int col = wn * 32 + nt * 8 + tg * 2;
            float2 v0 = make_float2(acc[mt][nt][0] + bias_s[col],
                                    acc[mt][nt][1] + bias_s[col + 1]);
            float2 v1 = make_float2(acc[mt][nt][2] + bias_s[col],
                                    acc[mt][nt][3] + bias_s[col + 1]);
            *(float2*)(Cr0 + col) = v0;
            *(float2*)(Cr1 + col) = v1;
        }
    }
}

// ---------------- transpose attn_W (main branch) ----------------------------
__global__ __launch_bounds__(256) void transpose_kernel(
    const float* __restrict__ attn_W, float* __restrict__ Wt)
{
    gdc_launch();
    __shared__ float t[32][33];
    const int tx = threadIdx.x & 31, ty = threadIdx.x >> 5;
    int x = blockIdx.x * 32 + tx;
    int y0 = blockIdx.y * 32 + ty;
#pragma unroll
    for (int j = 0; j < 32; j += 8)
        t[ty + j][tx] = attn_W[(size_t)(y0 + j) * NH + x];
    __syncthreads();
    x = blockIdx.y * 32 + tx;
    y0 = blockIdx.x * 32 + ty;
#pragma unroll
    for (int j = 0; j < 32; j += 8)
        Wt[(size_t)(y0 + j) * NH + x] = t[tx][ty + j];
}

// ---------------- conv (side branch): fp16 weights + hL + preW repack -------
__global__ __launch_bounds__(256) void conv_kernel(
    const float* __restrict__ pre_W,
    const float* __restrict__ Wih0, const float* __restrict__ Whh0,
    const float* __restrict__ Wih1, const float* __restrict__ Whh1,
    const float* __restrict__ last_hidden)
{
    const int y = blockIdx.y;
    if (y < 32) {
        const int n = y * 32 + blockIdx.x;
        for (int k = threadIdx.x; k < CAT_LD; k += 256)
            g_preWh[(size_t)n * CAT_LD + k] =
                (k < NH + NM) ? __float2half(pre_W[(size_t)n * (NH + NM) + k])
                              : __half(0.f);
    } else {
        const int cta = (y - 32) * 32 + blockIdx.x;     // 0..1663
        const int base = cta * 2048 + threadIdx.x;
#pragma unroll
        for (int it = 0; it < 8; it++) {
            const int e = base + it * 256;
            const float* src; __half* dst; int le;
            if (e < W4)            { src = Wih0; dst = g_Wih0h; le = e; }
            else if (e < 2 * W4)   { src = Whh0; dst = g_Whh0h; le = e - W4; }
            else if (e < 3 * W4)   { src = Wih1; dst = g_Wih1h; le = e - 2 * W4; }
            else if (e < 4 * W4)   { src = Whh1; dst = g_Whh1h; le = e - 3 * W4; }
            else                   { src = last_hidden; dst = g_hLh; le = e - 4 * W4; }
            float4 v = ((const float4*)src)[le];
            __half2* d2 = (__half2*)dst + (size_t)le * 2;
            d2[0] = __floats2half2_rn(v.x, v.y);
            d2[1] = __floats2half2_rn(v.z, v.w);
        }
    }
}

__device__ __forceinline__ float warp_sum(float v) {
#pragma unroll
    for (int o = 16; o; o >>= 1) v += __shfl_xor_sync(0xffffffffu, v, o);
    return v;
}

// ---------------- fused attention: 8-way u-reduce + online softmax ----------
__global__ __launch_bounds__(256, 3) void attn_fused(
    const float* __restrict__ enc, const float* __restrict__ upart,
    const float* __restrict__ motion, float* __restrict__ attn_out,
    __half* __restrict__ cath)
{
    gdc_launch();
    const int b = blockIdx.x;
    const int tid = threadIdx.x;
    const int lane = tid & 31, w = tid >> 5;

    __shared__ float e_raw[NS];
    __shared__ float warp_m[8], warp_z[8];
    __shared__ __align__(16) float ur_s[NH];
    __shared__ __align__(16) float ctxs[8 * NH];

    gdc_wait();
    {
        float4 v = make_float4(0.f, 0.f, 0.f, 0.f);
#pragma unroll
        for (int s = 0; s < 8; s++) {
            float4 p = ((const float4*)(upart + (size_t)s * NBNH +
                                        (size_t)b * NH))[tid];
            v.x += p.x; v.y += p.y; v.z += p.z; v.w += p.w;
        }
        ((float4*)ur_s)[tid] = v;
    }
    __syncthreads();

    float4 cacc[8];
#pragma unroll
    for (int i = 0; i < 8; i++) cacc[i] = make_float4(0.f, 0.f, 0.f, 0.f);
    float m = -1e30f, Z = 0.f;
    const float4* u4 = (const float4*)ur_s;

#pragma unroll
    for (int si = 0; si < 8; si++) {
        const int s = w + si * 8;
        const float4* ep = (const float4*)(enc + ((size_t)s * NB + b) * NH);
        float4 row[8];
        float d = 0.f;
#pragma unroll
        for (int i = 0; i < 8; i++) {
            row[i] = ep[i * 32 + lane];
            float4 uv = u4[i * 32 + lane];
            d = fmaf(row[i].x, uv.x, d);
            d = fmaf(row[i].y, uv.y, d);
            d = fmaf(row[i].z, uv.z, d);
            d = fmaf(row[i].w, uv.w, d);
        }
        d = warp_sum(d);
        if (lane == 0) e_raw[s] = d;
        const float mn = fmaxf(m, d);
        const float scale = __expf(m - mn);
        const float wgt = __expf(d - mn);
        Z = Z * scale + wgt;
#pragma unroll
        for (int i = 0; i < 8; i++) {
            cacc[i].x = fmaf(cacc[i].x, scale, wgt * row[i].x);
            cacc[i].y = fmaf(cacc[i].y, scale, wgt * row[i].y);
            cacc[i].z = fmaf(cacc[i].z, scale, wgt * row[i].z);
            cacc[i].w = fmaf(cacc[i].w, scale, wgt * row[i].w);
        }
        m = mn;
    }

    if (lane == 0) { warp_m[w] = m; warp_z[w] = Z; }
    float4* cs = (float4*)(ctxs + w * NH);
#pragma unroll
    for (int i = 0; i < 8; i++) cs[i * 32 + lane] = cacc[i];
    __syncthreads();

    float gm = warp_m[0];
#pragma unroll
    for (int ww = 1; ww < 8; ww++) gm = fmaxf(gm, warp_m[ww]);
    float gZ = 0.f;
#pragma unroll
    for (int ww = 0; ww < 8; ww++) gZ += warp_z[ww] * __expf(warp_m[ww] - gm);
    const float invZ = 1.f / gZ;

    if (tid < NS) attn_out[(size_t)b * NS + tid] = __expf(e_raw[tid] - gm) * invZ;
    if (tid < NM)
        cath[(size_t)b * CAT_LD + tid] = __float2half(motion[(size_t)b * NM + tid]);
    if (tid < CAT_LD - NH - NM)
        cath[(size_t)b * CAT_LD + NH + NM + tid] = __half(0.f);

    float4 a = make_float4(0.f, 0.f, 0.f, 0.f);
#pragma unroll
    for (int ww = 0; ww < 8; ww++) {
        const float sc = __expf(warp_m[ww] - gm);
        float4 v = *(const float4*)&ctxs[ww * NH + tid * 4];
        a.x = fmaf(v.x, sc, a.x);
        a.y = fmaf(v.y, sc, a.y);
        a.z = fmaf(v.z, sc, a.z);
        a.w = fmaf(v.w, sc, a.w);
    }
    __half* cp = cath + (size_t)b * CAT_LD + NM + tid * 4;
    *(__half2*)cp       = __floats2half2_rn(a.x * invZ, a.y * invZ);
    *(__half2*)(cp + 2) = __floats2half2_rn(a.z * invZ, a.w * invZ);
}

// ---------------- x0 split-K reduce (6 partials) -> fp16 --------------------
__global__ __launch_bounds__(256) void xreduce(const float* __restrict__ p,
                                               __half* __restrict__ x0h)
{
    gdc_launch();
    gdc_wait();
    const int i = (blockIdx.x * 256 + threadIdx.x) * 4;
    float4 v = *(const float4*)(p + i);
#pragma unroll
    for (int s = 1; s < 6; s++) {
        float4 w = *(const float4*)(p + (size_t)s * NBNH + i);
        v.x += w.x; v.y += w.y; v.z += w.z; v.w += w.w;
    }
    *(__half2*)(x0h + i)     = __floats2half2_rn(v.x, v.y);
    *(__half2*)(x0h + i + 2) = __floats2half2_rn(v.z, v.w);
}

// ---------------- GRU gate pointwise (layer 0, 3-way split gi) --------------
__global__ __launch_bounds__(256) void gate_kernel(
    const float* __restrict__ giA, const float* __restrict__ giB,
    const float* __restrict__ giC, const float* __restrict__ gh,
    const float* __restrict__ hprev, float* __restrict__ out_h,
    __half* __restrict__ out_h16)
{
    gdc_launch();
    gdc_wait();
    const int idx = blockIdx.x * blockDim.x + threadIdx.x;
    const int b = idx >> 10, n = idx & (NH - 1);
    const size_t o = (size_t)b * G3 + n;
    float ir = giA[o] + giB[o] + giC[o];
    float iz = giA[o + NH] + giB[o + NH] + giC[o + NH];
    float inn = giA[o + 2 * NH] + giB[o + 2 * NH] + giC[o + 2 * NH];
    float hr = gh[o], hz = gh[o + NH], hn = gh[o + 2 * NH];
    float r = 1.f / (1.f + expf(-(ir + hr)));
    float z = 1.f / (1.f + expf(-(iz + hz)));
    float nn = tanhf(inn + r * hn);
    float h = (1.f - z) * nn + z * hprev[idx];
    out_h[idx] = h;
    out_h16[idx] = __float2half(h);
}

// ---------------- fused gate(layer 1, 3-way split-K gi) + post linear -------
__global__ __launch_bounds__(256) void gatepost_kernel(
    const float* __restrict__ giA, const float* __restrict__ giB,
    const float* __restrict__ giC, const float* __restrict__ gh,
    const float* __restrict__ hprev, float* __restrict__ out_h,
    const float* __restrict__ W, const float* __restrict__ bias,
    float* __restrict__ out)
{
    gdc_launch();
    gdc_wait();
    const int b = blockIdx.x;
    const int tid = threadIdx.x;

    float hv[4];
#pragma unroll
    for (int q = 0; q < 4; q++) {
        const int n = tid * 4 + q;
        const size_t o = (size_t)b * G3 + n;
        float ir = giA[o] + giB[o] + giC[o];
        float iz = giA[o + NH] + giB[o + NH] + giC[o + NH];
        float inn = giA[o + 2 * NH] + giB[o + 2 * NH] + giC[o + 2 * NH];
        float hr = gh[o], hz = gh[o + NH], hn = gh[o + 2 * NH];
        float r = 1.f / (1.f + expf(-(ir + hr)));
        float z = 1.f / (1.f + expf(-(iz + hz)));
        float nn = tanhf(inn + r * hn);
        hv[q] = (1.f - z) * nn + z * hprev[(size_t)b * NH + n];
    }
    *(float4*)(out_h + (size_t)b * NH + tid * 4) =
        make_float4(hv[0], hv[1], hv[2], hv[3]);

    float acc[10];
#pragma unroll
    for (int o = 0; o < 10; o++) {
        const float4 wv = *(const float4*)(W + (size_t)o * NH + tid * 4);
        acc[o] = hv[0] * wv.x + hv[1] * wv.y + hv[2] * wv.z + hv[3] * wv.w;
    }
    __shared__ float red[10][8];
    const int lane = tid & 31, w = tid >> 5;
#pragma unroll
    for (int o = 0; o < 10; o++) {
        float v = warp_sum(acc[o]);
        if (lane == 0) red[o][w] = v;
    }
    __syncthreads();
    if (tid < 10) {
        float s = 0.f;
#pragma unroll
        for (int ww = 0; ww < 8; ww++) s += red[tid][ww];
        out[(size_t)b * 10 + tid] = s + bias[tid];
    }
}

// ---------------- host launch ------------------------------------------------
template <typename F, typename... Args>
static void pdl_launch(F kern, dim3 grid, dim3 block, size_t smem,
                       Args... args)
{
    cudaLaunchConfig_t cfg = {};
    cfg.gridDim = grid;
    cfg.blockDim = block;
    cfg.dynamicSmemBytes = smem;
    cfg.stream = 0;
    cudaLaunchAttribute at[1];
    at[0].id = cudaLaunchAttributeProgrammaticStreamSerialization;
    at[0].val.programmaticStreamSerializationAllowed = 1;
    cfg.attrs = at;
    cfg.numAttrs = 1;
    cudaLaunchKernelEx(&cfg, kern, args...);
}

extern "C" void kernel_launch(void* const* d_in, const int* in_sizes, int n_in,
                              void* d_out, int out_size)
{
    const float* motion      = (const float*)d_in[0];
    const float* last_hidden = (const float*)d_in[1];
    const float* enc         = (const float*)d_in[2];
    const float* attn_W      = (const float*)d_in[3];
    /* d_in[4] = attn_b: unused (softmax shift-invariant) */
    const float* pre_W  = (const float*)d_in[5];
    const float* pre_b  = (const float*)d_in[6];
    const float* Wih0   = (const float*)d_in[7];
    const float* Whh0   = (const float*)d_in[8];
    const float* bih0   = (const float*)d_in[9];
    const float* bhh0   = (const float*)d_in[10];
    const float* Wih1   = (const float*)d_in[11];
    const float* Whh1   = (const float*)d_in[12];
    const float* bih1   = (const float*)d_in[13];
    const float* bhh1   = (const float*)d_in[14];
    const float* post_W = (const float*)d_in[15];
    const float* post_b = (const float*)d_in[16];

    float* out        = (float*)d_out;
    float* out_output = out;
    float* out_h0     = out + NB * 10;
    float* out_h1     = out + NB * 10 + NBNH;
    float* out_attn   = out + NB * 10 + 2 * NBNH;

    float *upart, *xpart, *gi0A, *gi0B, *gi0C, *gh0, *gh1;
    float *gi1A, *gi1B, *gi1C, *Wt;
    __half *preWh, *Wih0h, *Whh0h, *Wih1h, *Whh1h, *hLh, *cath, *x0h, *h0h;
    cudaGetSymbolAddress((void**)&upart, g_upart);
    cudaGetSymbolAddress((void**)&xpart, g_xpart);
    cudaGetSymbolAddress((void**)&gi0A,  g_gi0A);
    cudaGetSymbolAddress((void**)&gi0B,  g_gi0B);
    cudaGetSymbolAddress((void**)&gi0C,  g_gi0C);
    cudaGetSymbolAddress((void**)&gh0,   g_gh0);
    cudaGetSymbolAddress((void**)&gh1,   g_gh1);
    cudaGetSymbolAddress((void**)&gi1A,  g_gi1A);
    cudaGetSymbolAddress((void**)&gi1B,  g_gi1B);
    cudaGetSymbolAddress((void**)&gi1C,  g_gi1C);
    cudaGetSymbolAddress((void**)&Wt,    g_Wt);
    cudaGetSymbolAddress((void**)&preWh, g_preWh);
    cudaGetSymbolAddress((void**)&Wih0h, g_Wih0h);
    cudaGetSymbolAddress((void**)&Whh0h, g_Whh0h);
    cudaGetSymbolAddress((void**)&Wih1h, g_Wih1h);
    cudaGetSymbolAddress((void**)&Whh1h, g_Whh1h);
    cudaGetSymbolAddress((void**)&hLh,   g_hLh);
    cudaGetSymbolAddress((void**)&cath,  g_cath);
    cudaGetSymbolAddress((void**)&x0h,   g_x0h);
    cudaGetSymbolAddress((void**)&h0h,   g_h0h);

    const float* hL1 = last_hidden + NBNH;
    const __half* hL0h = hLh;
    const __half* hL1h = hLh + NBNH;

    cudaFuncSetAttribute(gemm_mma, cudaFuncAttributeMaxDynamicSharedMemorySize,
                         DYN_SMEM);
    cudaFuncSetAttribute(gemm_h16, cudaFuncAttributeMaxDynamicSharedMemorySize,
                         DYN_SMEM);

    // ---- fork a side stream inside graph capture (host ops run once) ----
    cudaStream_t s2;
    cudaStreamCreateWithFlags(&s2, cudaStreamNonBlocking);
    cudaEvent_t eF, eC, eG;
    cudaEventCreateWithFlags(&eF, cudaEventDisableTiming);
    cudaEventCreateWithFlags(&eC, cudaEventDisableTiming);
    cudaEventCreateWithFlags(&eG, cudaEventDisableTiming);
    cudaEventRecord(eF, 0);
    cudaStreamWaitEvent(s2, eF, 0);

    // ---- SIDE branch: conv (weights->fp16, preW repack) -> gh0+gh1 ----
    conv_kernel<<<dim3(32, 84), 256, 0, s2>>>(pre_W, Wih0, Whh0, Wih1, Whh1,
                                              last_hidden);
    cudaEventRecord(eC, s2);
    {
        JobsH j = {};
        j.A[0] = hL0h; j.B[0] = Whh0h; j.bias[0] = bhh0; j.C[0] = gh0;
        j.A[1] = hL1h; j.B[1] = Whh1h; j.bias[1] = bhh1; j.C[1] = gh1;
        for (int s = 0; s < 2; s++) {
            j.lda[s] = NH; j.ldb[s] = NH; j.ldc[s] = G3;
            j.nchunk[s] = 32; j.nx[s] = 24;
        }
        gemm_h16<<<dim3(24, 4, 2), 256, DYN_SMEM, s2>>>(j);
    }
    cudaEventRecord(eG, s2);

    // ---- MAIN branch ----
    transpose_kernel<<<dim3(32, 32), 256>>>(attn_W, Wt);

    {   // u split-K x8 (split-tf32)
        Jobs j = {};
        for (int s = 0; s < 8; s++) {
            j.A[s] = hL1 + s * 128;  j.B[s] = Wt + s * 128;
            j.bias[s] = nullptr;     j.C[s] = upart + (size_t)s * NBNH;
            j.lda[s] = NH; j.ldb[s] = NH; j.ldc[s] = NH;
            j.nchunk[s] = 8; j.nx[s] = 8; j.split[s] = 1;
        }
        pdl_launch(gemm_mma, dim3(8, 4, 8), dim3(256), DYN_SMEM, j);
    }

    pdl_launch(attn_fused, dim3(NB), dim3(256), 0,
               enc, (const float*)upart, motion, out_attn, cath);

    cudaStreamWaitEvent(0, eC, 0);    // preWh ready

    {   // pre split-K x6
        JobsH j = {};
        const int koff[6] = {0, 192, 384, 576, 736, 896};
        const int nch[6]  = {6, 6, 6, 5, 5, 5};
        for (int s = 0; s < 6; s++) {
            j.A[s] = cath + koff[s]; j.B[s] = preWh + koff[s];
            j.bias[s] = (s == 0) ? pre_b : nullptr;
            j.C[s] = xpart + (size_t)s * NBNH;
            j.lda[s] = CAT_LD; j.ldb[s] = CAT_LD; j.ldc[s] = NH;
            j.nchunk[s] = nch[s]; j.nx[s] = 8;
        }
        pdl_launch(gemm_h16, dim3(8, 4, 6), dim3(256), DYN_SMEM, j);
    }
    pdl_launch(xreduce, dim3(NBNH / 1024), dim3(256), 0,
               (const float*)xpart, x0h);

    {   // gi0 split-K x3
        JobsH j = {};
        const int koff[3] = {0, 352, 704};
        const int nch[3] = {11, 11, 10};
        float* dst[3] = {gi0A, gi0B, gi0C};
        for (int k = 0; k < 3; k++) {
            j.A[k] = x0h + koff[k]; j.B[k] = Wih0h + koff[k];
            j.bias[k] = k ? nullptr : bih0;
            j.C[k] = dst[k];
            j.lda[k] = NH; j.ldb[k] = NH; j.ldc[k] = G3;
            j.nchunk[k] = nch[k]; j.nx[k] = 24;
        }
        pdl_launch(gemm_h16, dim3(24, 4, 3), dim3(256), DYN_SMEM, j);
    }

    cudaStreamWaitEvent(0, eG, 0);    // gh0/gh1 ready

    pdl_launch(gate_kernel, dim3(NBNH / 256), dim3(256), 0,
               (const float*)gi0A, (const float*)gi0B, (const float*)gi0C,
               (const float*)gh0, last_hidden, out_h0, h0h);

    {   // gi1 split-K x3
        JobsH j = {};
        const int koff[3] = {0, 352, 704};
        const int nch[3] = {11, 11, 10};
        float* dst[3] = {gi1A, gi1B, gi1C};
        for (int k = 0; k < 3; k++) {
            j.A[k] = h0h + koff[k]; j.B[k] = Wih1h + koff[k];
            j.bias[k] = k ? nullptr : bih1;
            j.C[k] = dst[k];
            j.lda[k] = NH; j.ldb[k] = NH; j.ldc[k] = G3;
            j.nchunk[k] = nch[k]; j.nx[k] = 24;
        }
        pdl_launch(gemm_h16, dim3(24, 4, 3), dim3(256), DYN_SMEM, j);
    }

    pdl_launch(gatepost_kernel, dim3(NB), dim3(256), 0,
               (const float*)gi1A, (const float*)gi1B, (const float*)gi1C,
               (const float*)gh1, hL1, out_h1, post_W, post_b, out_output);
}

// round 17
// speedup vs baseline: 1.3640x; 1.0335x over previous
#include <cuda_runtime.h>
#include <cuda_fp16.h>
#include <math.h>
#include <stdint.h>

#define NB 512
#define NH 1024
#define NS 64
#define NM 10
#define CAT_LD 1056
#define NBNH (NB * NH)
#define G3 (3 * NH)
#define NJOBS 12
#define W4 786432                     // G3*NH/4

// ---------------- scratch (device globals) ----------------------------------
__device__ __align__(1024) __half g_Wth[NH * NH];      // attn_W^T fp16 (hi)
__device__ __align__(1024) __half g_Wtlo[NH * NH];     // attn_W^T fp16 residual
__device__ __align__(1024) __half g_hLlo[NBNH];        // hL1 fp16 residual
__device__ __align__(1024) __half g_preWh[NH * CAT_LD];
__device__ __align__(1024) __half g_Wih0h[G3 * NH];
__device__ __align__(1024) __half g_Whh0h[G3 * NH];
__device__ __align__(1024) __half g_Wih1h[G3 * NH];
__device__ __align__(1024) __half g_Whh1h[G3 * NH];
__device__ __align__(1024) __half g_hLh[2 * NBNH];
__device__ __align__(1024) float  g_upart[12 * NBNH];
__device__ __align__(1024) __half g_cath[NB * CAT_LD];
__device__ __align__(1024) float  g_xpart[6 * NBNH];
__device__ __align__(1024) __half g_x0h[NBNH];
__device__ __align__(1024) __half g_h0h[NBNH];
__device__ __align__(1024) float  g_gi0A[NB * G3];
__device__ __align__(1024) float  g_gi0B[NB * G3];
__device__ __align__(1024) float  g_gi0C[NB * G3];
__device__ __align__(1024) float  g_gh0[NB * G3];
__device__ __align__(1024) float  g_gh1[NB * G3];
__device__ __align__(1024) float  g_gi1A[NB * G3];
__device__ __align__(1024) float  g_gi1B[NB * G3];
__device__ __align__(1024) float  g_gi1C[NB * G3];

struct JobsH {
    const __half* A[NJOBS]; const __half* B[NJOBS];
    const float* bias[NJOBS]; float* C[NJOBS];
    int lda[NJOBS], ldb[NJOBS], ldc[NJOBS], nchunk[NJOBS], nx[NJOBS];
};

// ---------------- helpers ----------------------------------------------------
__device__ __forceinline__ void gdc_launch() {
    asm volatile("griddepcontrol.launch_dependents;" ::: "memory");
}
__device__ __forceinline__ void gdc_wait() {
    asm volatile("griddepcontrol.wait;" ::: "memory");
}
__device__ __forceinline__ uint32_t smem_u32(const void* p) {
    uint32_t a;
    asm("{ .reg .u64 t; cvta.to.shared.u64 t, %1; cvt.u32.u64 %0, t; }"
        : "=r"(a) : "l"(p));
    return a;
}
__device__ __forceinline__ void mma_f16(float* c, uint32_t a0, uint32_t a1,
                                        uint32_t a2, uint32_t a3,
                                        uint32_t b0, uint32_t b1) {
    asm volatile(
        "mma.sync.aligned.m16n8k16.row.col.f32.f16.f16.f32 "
        "{%0,%1,%2,%3}, {%4,%5,%6,%7}, {%8,%9}, {%0,%1,%2,%3};"
        : "+f"(c[0]), "+f"(c[1]), "+f"(c[2]), "+f"(c[3])
        : "r"(a0), "r"(a1), "r"(a2), "r"(a3), "r"(b0), "r"(b1));
}
__device__ __forceinline__ void cp16(uint32_t dst, const void* src) {
    asm volatile("cp.async.cg.shared.global [%0], [%1], 16;"
                 :: "r"(dst), "l"(src));
}
__device__ __forceinline__ void ldsm4(uint32_t& r0, uint32_t& r1, uint32_t& r2,
                                      uint32_t& r3, uint32_t addr) {
    asm volatile("ldmatrix.sync.aligned.m8n8.x4.shared.b16 {%0,%1,%2,%3}, [%4];"
                 : "=r"(r0), "=r"(r1), "=r"(r2), "=r"(r3) : "r"(addr));
}
__device__ __forceinline__ __half2 lo_residual2(float x, float y, __half2 hi) {
    float2 hf = __half22float2(hi);
    return __floats2half2_rn(x - hf.x, y - hf.y);
}

#define NSTAGE 4
#define STG_B 20480
#define DYN_SMEM (NSTAGE * STG_B)   // 81920

// ---------------- fp16 GEMM (job-table batched) ------------------------------
__global__ __launch_bounds__(256, 2) void gemm_h16(JobsH jobs)
{
    gdc_launch();
    const int z = blockIdx.z;
    if (blockIdx.x >= jobs.nx[z]) { gdc_wait(); return; }

    extern __shared__ float dyn[];
    __shared__ float bias_s[128];

    const __half* A = jobs.A[z];
    const __half* B = jobs.B[z];
    const float* bias = jobs.bias[z];
    float* C = jobs.C[z];
    const int lda = jobs.lda[z], ldb = jobs.ldb[z], ldc = jobs.ldc[z];
    const int nchunk = jobs.nchunk[z];

    const int tid = threadIdx.x;
    const int wid = tid >> 5, lane = tid & 31;
    const int g = lane >> 2, tg = lane & 3;
    const int wm = wid >> 2, wn = wid & 3;
    const int n0 = blockIdx.x * 128;
    const int m0 = blockIdx.y * 128;

    if (tid < 128) bias_s[tid] = bias ? bias[n0 + tid] : 0.f;

    const uint32_t smem_base = smem_u32(dyn);
    const uint32_t a_off = (uint32_t)(((wm * 64 + (lane & 15)) * 40 +
                                       (lane >> 4) * 8) * 2);
    const uint32_t b_off = (uint32_t)(10240 +
        ((wn * 32 + (lane & 7) + ((lane >> 4) << 3)) * 40 +
         ((lane >> 3) & 1) * 8) * 2);

    const int lr0 = tid >> 1;
    const int sg0 = (tid & 1) * 2;

    auto load_chunk = [&](int c, int s) {
        const uint32_t sa = smem_base + s * STG_B;
        const uint32_t sb = sa + 10240;
        const __half* Ag = A + (size_t)m0 * lda + c * 32;
        const __half* Bg = B + (size_t)n0 * ldb + c * 32;
#pragma unroll
        for (int q = 0; q < 2; q++) {
            const int sg = sg0 + q;
            cp16(sa + (lr0 * 40 + sg * 8) * 2, Ag + (size_t)lr0 * lda + sg * 8);
            cp16(sb + (lr0 * 40 + sg * 8) * 2, Bg + (size_t)lr0 * ldb + sg * 8);
        }
        asm volatile("cp.async.commit_group;" ::: "memory");
    };

    float acc[4][4][4];
#pragma unroll
    for (int mt = 0; mt < 4; mt++)
#pragma unroll
        for (int nt = 0; nt < 4; nt++)
#pragma unroll
            for (int q = 0; q < 4; q++) acc[mt][nt][q] = 0.f;

    gdc_wait();
    load_chunk(0, 0);
    if (nchunk > 1) load_chunk(1, 1);
    if (nchunk > 2) load_chunk(2, 2);

    for (int t = 0; t < nchunk; t++) {
        if (t < nchunk - 2)
            asm volatile("cp.async.wait_group 2;" ::: "memory");
        else if (t == nchunk - 2)
            asm volatile("cp.async.wait_group 1;" ::: "memory");
        else
            asm volatile("cp.async.wait_group 0;" ::: "memory");
        __syncthreads();
        if (t + 3 < nchunk) load_chunk(t + 3, (t + 3) & 3);

        const uint32_t sbase = smem_base + (t & 3) * STG_B;
        const uint32_t abase = sbase + a_off;
        const uint32_t bbase = sbase + b_off;

#pragma unroll
        for (int ks = 0; ks < 2; ks++) {
            uint32_t au[4][4], bu[4][2];
#pragma unroll
            for (int mt = 0; mt < 4; mt++)
                ldsm4(au[mt][0], au[mt][1], au[mt][2], au[mt][3],
                      abase + mt * 1280 + ks * 32);
#pragma unroll
            for (int j = 0; j < 2; j++)
                ldsm4(bu[2 * j][0], bu[2 * j][1], bu[2 * j + 1][0],
                      bu[2 * j + 1][1], bbase + j * 1280 + ks * 32);
#pragma unroll
            for (int mt = 0; mt < 4; mt++)
#pragma unroll
                for (int nt = 0; nt < 4; nt++)
                    mma_f16(acc[mt][nt], au[mt][0], au[mt][1], au[mt][2],
                            au[mt][3], bu[nt][0], bu[nt][1]);
        }
    }

#pragma unroll
    for (int mt = 0; mt < 4; mt++) {
        const int row = m0 + wm * 64 + mt * 16 + g;
        float* Cr0 = C + (size_t)row * ldc + n0;
        float* Cr1 = Cr0 + 8 * ldc;
#pragma unroll
        for (int nt = 0; nt < 4; nt++) {
            const int col = wn * 32 + nt * 8 + tg * 2;
            float2 v0 = make_float2(acc[mt][nt][0] + bias_s[col],
                                    acc[mt][nt][1] + bias_s[col + 1]);
            float2 v1 = make_float2(acc[mt][nt][2] + bias_s[col],
                                    acc[mt][nt][3] + bias_s[col + 1]);
            *(float2*)(Cr0 + col) = v0;
            *(float2*)(Cr1 + col) = v1;
        }
    }
}

// ---------------- main-branch prep: attn_W^T->fp16 hi/lo + hL->fp16 (+lo) ---
__global__ __launch_bounds__(256) void trans_conv_kernel(
    const float* __restrict__ attn_W, const float* __restrict__ last_hidden)
{
    gdc_launch();
    const int y = blockIdx.y;
    if (y < 32) {
        __shared__ float t[32][33];
        const int tx = threadIdx.x & 31, ty = threadIdx.x >> 5;
        int x = blockIdx.x * 32 + tx;
        int y0 = y * 32 + ty;
#pragma unroll
        for (int j = 0; j < 32; j += 8)
            t[ty + j][tx] = attn_W[(size_t)(y0 + j) * NH + x];
        __syncthreads();
        x = y * 32 + tx;
        y0 = blockIdx.x * 32 + ty;
#pragma unroll
        for (int j = 0; j < 32; j += 8) {
            const float v = t[tx][ty + j];
            const __half h = __float2half(v);
            const size_t idx = (size_t)(y0 + j) * NH + x;
            g_Wth[idx]  = h;
            g_Wtlo[idx] = __float2half(v - __half2float(h));
        }
    } else {
        // hL convert: 262144 float4 over 256 CTAs; lo residual for hL1 half
        const int cta = (y - 32) * 32 + blockIdx.x;
        const int base = cta * 1024 + threadIdx.x;
#pragma unroll
        for (int it = 0; it < 4; it++) {
            const int e = base + it * 256;
            float4 v = ((const float4*)last_hidden)[e];
            __half2 h0 = __floats2half2_rn(v.x, v.y);
            __half2 h1 = __floats2half2_rn(v.z, v.w);
            __half2* d2 = (__half2*)g_hLh + (size_t)e * 2;
            d2[0] = h0;
            d2[1] = h1;
            if (e >= NBNH / 4) {   // hL1 region
                __half2* l2 = (__half2*)g_hLlo + (size_t)(e - NBNH / 4) * 2;
                l2[0] = lo_residual2(v.x, v.y, h0);
                l2[1] = lo_residual2(v.z, v.w, h1);
            }
        }
    }
}

// ---------------- side-branch conv: GRU weights fp16 + preW repack ----------
__global__ __launch_bounds__(256) void conv_kernel(
    const float* __restrict__ pre_W,
    const float* __restrict__ Wih0, const float* __restrict__ Whh0,
    const float* __restrict__ Wih1, const float* __restrict__ Whh1)
{
    const int y = blockIdx.y;
    if (y < 32) {
        const int n = y * 32 + blockIdx.x;
        for (int k = threadIdx.x; k < CAT_LD; k += 256)
            g_preWh[(size_t)n * CAT_LD + k] =
                (k < NH + NM) ? __float2half(pre_W[(size_t)n * (NH + NM) + k])
                              : __half(0.f);
    } else {
        const int cta = (y - 32) * 32 + blockIdx.x;     // 0..1535
        const int base = cta * 2048 + threadIdx.x;
#pragma unroll
        for (int it = 0; it < 8; it++) {
            const int e = base + it * 256;
            const float* src; __half* dst; int le;
            if (e < W4)            { src = Wih0; dst = g_Wih0h; le = e; }
            else if (e < 2 * W4)   { src = Whh0; dst = g_Whh0h; le = e - W4; }
            else if (e < 3 * W4)   { src = Wih1; dst = g_Wih1h; le = e - 2 * W4; }
            else                   { src = Whh1; dst = g_Whh1h; le = e - 3 * W4; }
            float4 v = ((const float4*)src)[le];
            __half2* d2 = (__half2*)dst + (size_t)le * 2;
            d2[0] = __floats2half2_rn(v.x, v.y);
            d2[1] = __floats2half2_rn(v.z, v.w);
        }
    }
}

__device__ __forceinline__ float warp_sum(float v) {
#pragma unroll
    for (int o = 16; o; o >>= 1) v += __shfl_xor_sync(0xffffffffu, v, o);
    return v;
}

// ---------------- fused attention: 12-way u-reduce + online softmax ---------
__global__ __launch_bounds__(256, 3) void attn_fused(
    const float* __restrict__ enc, const float* __restrict__ upart,
    const float* __restrict__ motion, float* __restrict__ attn_out,
    __half* __restrict__ cath)
{
    gdc_launch();
    const int b = blockIdx.x;
    const int tid = threadIdx.x;
    const int lane = tid & 31, w = tid >> 5;

    __shared__ float e_raw[NS];
    __shared__ float warp_m[8], warp_z[8];
    __shared__ __align__(16) float ur_s[NH];
    __shared__ __align__(16) float ctxs[8 * NH];

    gdc_wait();
    {
        float4 v = make_float4(0.f, 0.f, 0.f, 0.f);
#pragma unroll
        for (int s = 0; s < 12; s++) {
            float4 p = ((const float4*)(upart + (size_t)s * NBNH +
                                        (size_t)b * NH))[tid];
            v.x += p.x; v.y += p.y; v.z += p.z; v.w += p.w;
        }
        ((float4*)ur_s)[tid] = v;
    }
    __syncthreads();

    float4 cacc[8];
#pragma unroll
    for (int i = 0; i < 8; i++) cacc[i] = make_float4(0.f, 0.f, 0.f, 0.f);
    float m = -1e30f, Z = 0.f;
    const float4* u4 = (const float4*)ur_s;

#pragma unroll
    for (int si = 0; si < 8; si++) {
        const int s = w + si * 8;
        const float4* ep = (const float4*)(enc + ((size_t)s * NB + b) * NH);
        float4 row[8];
        float d = 0.f;
#pragma unroll
        for (int i = 0; i < 8; i++) {
            row[i] = ep[i * 32 + lane];
            float4 uv = u4[i * 32 + lane];
            d = fmaf(row[i].x, uv.x, d);
            d = fmaf(row[i].y, uv.y, d);
            d = fmaf(row[i].z, uv.z, d);
            d = fmaf(row[i].w, uv.w, d);
        }
        d = warp_sum(d);
        if (lane == 0) e_raw[s] = d;
        const float mn = fmaxf(m, d);
        const float scale = __expf(m - mn);
        const float wgt = __expf(d - mn);
        Z = Z * scale + wgt;
#pragma unroll
        for (int i = 0; i < 8; i++) {
            cacc[i].x = fmaf(cacc[i].x, scale, wgt * row[i].x);
            cacc[i].y = fmaf(cacc[i].y, scale, wgt * row[i].y);
            cacc[i].z = fmaf(cacc[i].z, scale, wgt * row[i].z);
            cacc[i].w = fmaf(cacc[i].w, scale, wgt * row[i].w);
        }
        m = mn;
    }

    if (lane == 0) { warp_m[w] = m; warp_z[w] = Z; }
    float4* cs = (float4*)(ctxs + w * NH);
#pragma unroll
    for (int i = 0; i < 8; i++) cs[i * 32 + lane] = cacc[i];
    __syncthreads();

    float gm = warp_m[0];
#pragma unroll
    for (int ww = 1; ww < 8; ww++) gm = fmaxf(gm, warp_m[ww]);
    float gZ = 0.f;
#pragma unroll
    for (int ww = 0; ww < 8; ww++) gZ += warp_z[ww] * __expf(warp_m[ww] - gm);
    const float invZ = 1.f / gZ;

    if (tid < NS) attn_out[(size_t)b * NS + tid] = __expf(e_raw[tid] - gm) * invZ;
    if (tid < NM)
        cath[(size_t)b * CAT_LD + tid] = __float2half(motion[(size_t)b * NM + tid]);
    if (tid < CAT_LD - NH - NM)
        cath[(size_t)b * CAT_LD + NH + NM + tid] = __half(0.f);

    float4 a = make_float4(0.f, 0.f, 0.f, 0.f);
#pragma unroll
    for (int ww = 0; ww < 8; ww++) {
        const float sc = __expf(warp_m[ww] - gm);
        float4 v = *(const float4*)&ctxs[ww * NH + tid * 4];
        a.x = fmaf(v.x, sc, a.x);
        a.y = fmaf(v.y, sc, a.y);
        a.z = fmaf(v.z, sc, a.z);
        a.w = fmaf(v.w, sc, a.w);
    }
    __half* cp = cath + (size_t)b * CAT_LD + NM + tid * 4;
    *(__half2*)cp       = __floats2half2_rn(a.x * invZ, a.y * invZ);
    *(__half2*)(cp + 2) = __floats2half2_rn(a.z * invZ, a.w * invZ);
}

// ---------------- x0 split-K reduce (6 partials) -> fp16 --------------------
__global__ __launch_bounds__(256) void xreduce(const float* __restrict__ p,
                                               __half* __restrict__ x0h)
{
    gdc_launch();
    gdc_wait();
    const int i = (blockIdx.x * 256 + threadIdx.x) * 4;
    float4 v = *(const float4*)(p + i);
#pragma unroll
    for (int s = 1; s < 6; s++) {
        float4 w = *(const float4*)(p + (size_t)s * NBNH + i);
        v.x += w.x; v.y += w.y; v.z += w.z; v.w += w.w;
    }
    *(__half2*)(x0h + i)     = __floats2half2_rn(v.x, v.y);
    *(__half2*)(x0h + i + 2) = __floats2half2_rn(v.z, v.w);
}

// ---------------- GRU gate pointwise (layer 0, 3-way split gi) --------------
__global__ __launch_bounds__(256) void gate_kernel(
    const float* __restrict__ giA, const float* __restrict__ giB,
    const float* __restrict__ giC, const float* __restrict__ gh,
    const float* __restrict__ hprev, float* __restrict__ out_h,
    __half* __restrict__ out_h16)
{
    gdc_launch();
    gdc_wait();
    const int idx = blockIdx.x * blockDim.x + threadIdx.x;
    const int b = idx >> 10, n = idx & (NH - 1);
    const size_t o = (size_t)b * G3 + n;
    float ir = giA[o] + giB[o] + giC[o];
    float iz = giA[o + NH] + giB[o + NH] + giC[o + NH];
    float inn = giA[o + 2 * NH] + giB[o + 2 * NH] + giC[o + 2 * NH];
    float hr = gh[o], hz = gh[o + NH], hn = gh[o + 2 * NH];
    float r = 1.f / (1.f + expf(-(ir + hr)));
    float z = 1.f / (1.f + expf(-(iz + hz)));
    float nn = tanhf(inn + r * hn);
    float h = (1.f - z) * nn + z * hprev[idx];
    out_h[idx] = h;
    out_h16[idx] = __float2half(h);
}

// ---------------- fused gate(layer 1, 3-way split-K gi) + post linear -------
__global__ __launch_bounds__(256) void gatepost_kernel(
    const float* __restrict__ giA, const float* __restrict__ giB,
    const float* __restrict__ giC, const float* __restrict__ gh,
    const float* __restrict__ hprev, float* __restrict__ out_h,
    const float* __restrict__ W, const float* __restrict__ bias,
    float* __restrict__ out)
{
    gdc_launch();
    gdc_wait();
    const int b = blockIdx.x;
    const int tid = threadIdx.x;

    float hv[4];
#pragma unroll
    for (int q = 0; q < 4; q++) {
        const int n = tid * 4 + q;
        const size_t o = (size_t)b * G3 + n;
        float ir = giA[o] + giB[o] + giC[o];
        float iz = giA[o + NH] + giB[o + NH] + giC[o + NH];
        float inn = giA[o + 2 * NH] + giB[o + 2 * NH] + giC[o + 2 * NH];
        float hr = gh[o], hz = gh[o + NH], hn = gh[o + 2 * NH];
        float r = 1.f / (1.f + expf(-(ir + hr)));
        float z = 1.f / (1.f + expf(-(iz + hz)));
        float nn = tanhf(inn + r * hn);
        hv[q] = (1.f - z) * nn + z * hprev[(size_t)b * NH + n];
    }
    *(float4*)(out_h + (size_t)b * NH + tid * 4) =
        make_float4(hv[0], hv[1], hv[2], hv[3]);

    float acc[10];
#pragma unroll
    for (int o = 0; o < 10; o++) {
        const float4 wv = *(const float4*)(W + (size_t)o * NH + tid * 4);
        acc[o] = hv[0] * wv.x + hv[1] * wv.y + hv[2] * wv.z + hv[3] * wv.w;
    }
    __shared__ float red[10][8];
    const int lane = tid & 31, w = tid >> 5;
#pragma unroll
    for (int o = 0; o < 10; o++) {
        float v = warp_sum(acc[o]);
        if (lane == 0) red[o][w] = v;
    }
    __syncthreads();
    if (tid < 10) {
        float s = 0.f;
#pragma unroll
        for (int ww = 0; ww < 8; ww++) s += red[tid][ww];
        out[(size_t)b * 10 + tid] = s + bias[tid];
    }
}

// ---------------- host launch ------------------------------------------------
template <typename F, typename... Args>
static void pdl_launch(F kern, dim3 grid, dim3 block, size_t smem,
                       Args... args)
{
    cudaLaunchConfig_t cfg = {};
    cfg.gridDim = grid;
    cfg.blockDim = block;
    cfg.dynamicSmemBytes = smem;
    cfg.stream = 0;
    cudaLaunchAttribute at[1];
    at[0].id = cudaLaunchAttributeProgrammaticStreamSerialization;
    at[0].val.programmaticStreamSerializationAllowed = 1;
    cfg.attrs = at;
    cfg.numAttrs = 1;
    cudaLaunchKernelEx(&cfg, kern, args...);
}

extern "C" void kernel_launch(void* const* d_in, const int* in_sizes, int n_in,
                              void* d_out, int out_size)
{
    const float* motion      = (const float*)d_in[0];
    const float* last_hidden = (const float*)d_in[1];
    const float* enc         = (const float*)d_in[2];
    const float* attn_W      = (const float*)d_in[3];
    /* d_in[4] = attn_b: unused (softmax shift-invariant) */
    const float* pre_W  = (const float*)d_in[5];
    const float* pre_b  = (const float*)d_in[6];
    const float* Wih0   = (const float*)d_in[7];
    const float* Whh0   = (const float*)d_in[8];
    const float* bih0   = (const float*)d_in[9];
    const float* bhh0   = (const float*)d_in[10];
    const float* Wih1   = (const float*)d_in[11];
    const float* Whh1   = (const float*)d_in[12];
    const float* bih1   = (const float*)d_in[13];
    const float* bhh1   = (const float*)d_in[14];
    const float* post_W = (const float*)d_in[15];
    const float* post_b = (const float*)d_in[16];

    float* out        = (float*)d_out;
    float* out_output = out;
    float* out_h0     = out + NB * 10;
    float* out_h1     = out + NB * 10 + NBNH;
    float* out_attn   = out + NB * 10 + 2 * NBNH;

    float *upart, *xpart, *gi0A, *gi0B, *gi0C, *gh0, *gh1;
    float *gi1A, *gi1B, *gi1C;
    __half *Wth, *Wtlo, *hLlo, *preWh, *Wih0h, *Whh0h, *Wih1h, *Whh1h;
    __half *hLh, *cath, *x0h, *h0h;
    cudaGetSymbolAddress((void**)&upart, g_upart);
    cudaGetSymbolAddress((void**)&xpart, g_xpart);
    cudaGetSymbolAddress((void**)&gi0A,  g_gi0A);
    cudaGetSymbolAddress((void**)&gi0B,  g_gi0B);
    cudaGetSymbolAddress((void**)&gi0C,  g_gi0C);
    cudaGetSymbolAddress((void**)&gh0,   g_gh0);
    cudaGetSymbolAddress((void**)&gh1,   g_gh1);
    cudaGetSymbolAddress((void**)&gi1A,  g_gi1A);
    cudaGetSymbolAddress((void**)&gi1B,  g_gi1B);
    cudaGetSymbolAddress((void**)&gi1C,  g_gi1C);
    cudaGetSymbolAddress((void**)&Wth,   g_Wth);
    cudaGetSymbolAddress((void**)&Wtlo,  g_Wtlo);
    cudaGetSymbolAddress((void**)&hLlo,  g_hLlo);
    cudaGetSymbolAddress((void**)&preWh, g_preWh);
    cudaGetSymbolAddress((void**)&Wih0h, g_Wih0h);
    cudaGetSymbolAddress((void**)&Whh0h, g_Whh0h);
    cudaGetSymbolAddress((void**)&Wih1h, g_Wih1h);
    cudaGetSymbolAddress((void**)&Whh1h, g_Whh1h);
    cudaGetSymbolAddress((void**)&hLh,   g_hLh);
    cudaGetSymbolAddress((void**)&cath,  g_cath);
    cudaGetSymbolAddress((void**)&x0h,   g_x0h);
    cudaGetSymbolAddress((void**)&h0h,   g_h0h);

    const float* hL1 = last_hidden + NBNH;
    const __half* hL0h = hLh;
    const __half* hL1h = hLh + NBNH;

    cudaFuncSetAttribute(gemm_h16, cudaFuncAttributeMaxDynamicSharedMemorySize,
                         DYN_SMEM);

    // ---- fork side stream inside capture ----
    cudaStream_t s2;
    cudaStreamCreateWithFlags(&s2, cudaStreamNonBlocking);
    cudaEvent_t eF, eC, eG, eH;
    cudaEventCreateWithFlags(&eF, cudaEventDisableTiming);
    cudaEventCreateWithFlags(&eC, cudaEventDisableTiming);
    cudaEventCreateWithFlags(&eG, cudaEventDisableTiming);
    cudaEventCreateWithFlags(&eH, cudaEventDisableTiming);
    cudaEventRecord(eF, 0);
    cudaStreamWaitEvent(s2, eF, 0);

    // ---- SIDE: conv (GRU weights fp16 + preW repack) ----
    conv_kernel<<<dim3(32, 80), 256, 0, s2>>>(pre_W, Wih0, Whh0, Wih1, Whh1);
    cudaEventRecord(eC, s2);

    // ---- MAIN: transpose attn_W -> fp16 hi/lo + hL -> fp16 (+lo for hL1) ----
    trans_conv_kernel<<<dim3(32, 40), 256>>>(attn_W, last_hidden);
    cudaEventRecord(eH, 0);

    // ---- SIDE (cont): gh0 + gh1 ----
    cudaStreamWaitEvent(s2, eH, 0);
    {
        JobsH j = {};
        j.A[0] = hL0h; j.B[0] = Whh0h; j.bias[0] = bhh0; j.C[0] = gh0;
        j.A[1] = hL1h; j.B[1] = Whh1h; j.bias[1] = bhh1; j.C[1] = gh1;
        for (int s = 0; s < 2; s++) {
            j.lda[s] = NH; j.ldb[s] = NH; j.ldc[s] = G3;
            j.nchunk[s] = 32; j.nx[s] = 24;
        }
        gemm_h16<<<dim3(24, 4, 2), 256, DYN_SMEM, s2>>>(j);
    }
    cudaEventRecord(eG, s2);

    // ---- MAIN: u via 2^-22 fp16 split: ah*bh + al*bh + ah*bl
    //      each product split-K x4 (8 chunks) -> 12 jobs, 384 CTAs ----
    {
        JobsH j = {};
        for (int p = 0; p < 3; p++) {
            const __half* Abase = (p == 1) ? hLlo : hL1h;
            const __half* Bbase = (p == 2) ? Wtlo : Wth;
            for (int s = 0; s < 4; s++) {
                const int idx = p * 4 + s;
                j.A[idx] = Abase + s * 256;
                j.B[idx] = Bbase + s * 256;
                j.bias[idx] = nullptr;
                j.C[idx] = upart + (size_t)idx * NBNH;
                j.lda[idx] = NH; j.ldb[idx] = NH; j.ldc[idx] = NH;
                j.nchunk[idx] = 8; j.nx[idx] = 8;
            }
        }
        pdl_launch(gemm_h16, dim3(8, 4, 12), dim3(256), DYN_SMEM, j);
    }

    pdl_launch(attn_fused, dim3(NB), dim3(256), 0,
               enc, (const float*)upart, motion, out_attn, cath);

    cudaStreamWaitEvent(0, eC, 0);    // preWh ready

    {   // pre split-K x6
        JobsH j = {};
        const int koff[6] = {0, 192, 384, 576, 736, 896};
        const int nch[6]  = {6, 6, 6, 5, 5, 5};
        for (int s = 0; s < 6; s++) {
            j.A[s] = cath + koff[s]; j.B[s] = preWh + koff[s];
            j.bias[s] = (s == 0) ? pre_b : nullptr;
            j.C[s] = xpart + (size_t)s * NBNH;
            j.lda[s] = CAT_LD; j.ldb[s] = CAT_LD; j.ldc[s] = NH;
            j.nchunk[s] = nch[s]; j.nx[s] = 8;
        }
        pdl_launch(gemm_h16, dim3(8, 4, 6), dim3(256), DYN_SMEM, j);
    }
    pdl_launch(xreduce, dim3(NBNH / 1024), dim3(256), 0,
               (const float*)xpart, x0h);

    {   // gi0 split-K x3
        JobsH j = {};
        const int koff[3] = {0, 352, 704};
        const int nch[3] = {11, 11, 10};
        float* dst[3] = {gi0A, gi0B, gi0C};
        for (int k = 0; k < 3; k++) {
            j.A[k] = x0h + koff[k]; j.B[k] = Wih0h + koff[k];
            j.bias[k] = k ? nullptr : bih0;
            j.C[k] = dst[k];
            j.lda[k] = NH; j.ldb[k] = NH; j.ldc[k] = G3;
            j.nchunk[k] = nch[k]; j.nx[k] = 24;
        }
        pdl_launch(gemm_h16, dim3(24, 4, 3), dim3(256), DYN_SMEM, j);
    }

    cudaStreamWaitEvent(0, eG, 0);    // gh0/gh1 ready

    pdl_launch(gate_kernel, dim3(NBNH / 256), dim3(256), 0,
               (const float*)gi0A, (const float*)gi0B, (const float*)gi0C,
               (const float*)gh0, last_hidden, out_h0, h0h);

    {   // gi1 split-K x3
        JobsH j = {};
        const int koff[3] = {0, 352, 704};
        const int nch[3] = {11, 11, 10};
        float* dst[3] = {gi1A, gi1B, gi1C};
        for (int k = 0; k < 3; k++) {
            j.A[k] = h0h + koff[k]; j.B[k] = Wih1h + koff[k];
            j.bias[k] = k ? nullptr : bih1;
            j.C[k] = dst[k];
            j.lda[k] = NH; j.ldb[k] = NH; j.ldc[k] = G3;
            j.nchunk[k] = nch[k]; j.nx[k] = 24;
        }
        pdl_launch(gemm_h16, dim3(24, 4, 3), dim3(256), DYN_SMEM, j);
    }

    pdl_launch(gatepost_kernel, dim3(NB), dim3(256), 0,
               (const float*)gi1A, (const float*)gi1B, (const float*)gi1C,
               (const float*)gh1, hL1, out_h1, post_W, post_b, out_output);
}